// round 10
// baseline (speedup 1.0000x reference)
#include <cuda_runtime.h>
#include <cuda_bf16.h>
#include <math.h>
#include <stdint.h>

// ---------------------------------------------------------------------------
#define ROWS 131072        // B*H*W tokens (= 2048 windows * 64)
#define HID  1024
#define MB   ((size_t)1024 * 1024)

#define POOL_BYTES ((size_t)836 * MB)
__device__ __align__(1024) unsigned char g_pool[POOL_BYTES];

#define OFF_QIN_F32  ((size_t)0)
#define OFF_Q_BF     ((size_t)128 * MB)
#define OFF_KV_BF    ((size_t)256 * MB)
#define OFF_QIN_BF   ((size_t)512 * MB)
#define OFF_KVIN_BF  ((size_t)576 * MB)
#define OFF_ATT_BF   ((size_t)640 * MB)
#define OFF_X1_F32   ((size_t)704 * MB)
#define OFF_WQ_BF    ((size_t)832 * MB)
#define OFF_WKV_BF   (OFF_WQ_BF  + 256 * 256 * 2)
#define OFF_W_P_BF   (OFF_WKV_BF + 512 * 256 * 2)
#define OFF_W1_BF    (OFF_W_P_BF + 256 * 256 * 2)
#define OFF_W2_BF    (OFF_W1_BF  + 1024 * 256 * 2)
#define OFF_BIASF    (OFF_W2_BF  + 1024 * 256 * 2)   // [8][64][64] f32 = 128KB
#define OFF_HID_BF   ((size_t)0)
#define OFF_YN_BF    ((size_t)256 * MB)

// SW128 swizzle for 128B-row bf16 tiles
#define SWZ(o) ((o) ^ (((o) >> 3) & 0x70))

// ---------------------------------------------------------------------------
// PTX helpers (baseline sm_100-safe)
// ---------------------------------------------------------------------------
__device__ __forceinline__ uint32_t smem_u32(const void* p) {
    uint32_t a;
    asm("{ .reg .u64 t; cvta.to.shared.u64 t, %1; cvt.u32.u64 %0, t; }" : "=r"(a) : "l"(p));
    return a;
}
__device__ __forceinline__ void cp16(uint32_t s, const void* g) {
    asm volatile("cp.async.cg.shared.global [%0], [%1], 16;" :: "r"(s), "l"(g) : "memory");
}
__device__ __forceinline__ void cp_commit() { asm volatile("cp.async.commit_group;" ::: "memory"); }
template<int N> __device__ __forceinline__ void cp_wait() {
    asm volatile("cp.async.wait_group %0;" :: "n"(N) : "memory");
}
__device__ __forceinline__ void ldm_x4(uint32_t& r0, uint32_t& r1, uint32_t& r2, uint32_t& r3, uint32_t addr) {
    asm volatile("ldmatrix.sync.aligned.m8n8.x4.shared.b16 {%0,%1,%2,%3}, [%4];"
                 : "=r"(r0), "=r"(r1), "=r"(r2), "=r"(r3) : "r"(addr));
}
__device__ __forceinline__ void ldm_x4t(uint32_t& r0, uint32_t& r1, uint32_t& r2, uint32_t& r3, uint32_t addr) {
    asm volatile("ldmatrix.sync.aligned.m8n8.x4.trans.shared.b16 {%0,%1,%2,%3}, [%4];"
                 : "=r"(r0), "=r"(r1), "=r"(r2), "=r"(r3) : "r"(addr));
}
__device__ __forceinline__ void mma_bf16(float* c, const uint32_t* a, uint32_t b0, uint32_t b1) {
    asm volatile(
        "mma.sync.aligned.m16n8k16.row.col.f32.bf16.bf16.f32 "
        "{%0,%1,%2,%3}, {%4,%5,%6,%7}, {%8,%9}, {%0,%1,%2,%3};"
        : "+f"(c[0]), "+f"(c[1]), "+f"(c[2]), "+f"(c[3])
        : "r"(a[0]), "r"(a[1]), "r"(a[2]), "r"(a[3]), "r"(b0), "r"(b1));
}
__device__ __forceinline__ uint32_t packbf(float a, float b) {
    __nv_bfloat162 p = __floats2bfloat162_rn(a, b);
    return *(uint32_t*)&p;
}

// ---------------------------------------------------------------------------
// Merged weight conversion: all 5 weights in one launch.
// ---------------------------------------------------------------------------
__global__ __launch_bounds__(256) void convall_kernel(
    const float* __restrict__ qw, const float* __restrict__ kvw,
    const float* __restrict__ pw, const float* __restrict__ w1,
    const float* __restrict__ w2,
    __nv_bfloat16* __restrict__ dq, __nv_bfloat16* __restrict__ dkv,
    __nv_bfloat16* __restrict__ dp, __nv_bfloat16* __restrict__ dw1,
    __nv_bfloat16* __restrict__ dw2)
{
    int blk = blockIdx.x;
    const float* src; __nv_bfloat16* dst; int K, base;
    if      (blk < 32)  { src = qw;  dst = dq;  K = 256;  base = 0;   }
    else if (blk < 96)  { src = kvw; dst = dkv; K = 256;  base = 32;  }
    else if (blk < 128) { src = pw;  dst = dp;  K = 256;  base = 96;  }
    else if (blk < 256) { src = w1;  dst = dw1; K = 256;  base = 128; }
    else                { src = w2;  dst = dw2; K = 1024; base = 256; }
    int gid = (blk - base) * 256 + threadIdx.x;
    int kdiv8 = K >> 3;
    int r  = gid / kdiv8;
    int c0 = (gid - r * kdiv8) << 3;
    const float4* s = (const float4*)(src + (size_t)r * K + c0);
    float4 f0 = s[0], f1 = s[1];
    uint4 v;
    v.x = packbf(f0.x, f0.y); v.y = packbf(f0.z, f0.w);
    v.z = packbf(f1.x, f1.y); v.w = packbf(f1.z, f1.w);
    int mt = r >> 7, kt = c0 >> 6, lr = r & 127, lc = c0 & 63;
    size_t tbase = ((size_t)(mt * (K >> 6) + kt)) << 14;
    uint32_t off = SWZ((uint32_t)(lr * 128 + lc * 2));
    *(uint4*)((unsigned char*)dst + tbase + off) = v;
}

// Expand rel-pos bias table -> biasf[8][64][64]
__global__ __launch_bounds__(64) void biasx_kernel(
    const float* __restrict__ btab, float* __restrict__ biasf)
{
    int n = blockIdx.x, m = threadIdx.x;
    int idx = (((n >> 3) - (m >> 3) + 7) * 15 + ((n & 7) - (m & 7) + 7)) * 8;
    #pragma unroll
    for (int h = 0; h < 8; h++)
        biasf[h * 4096 + n * 64 + m] = btab[idx + h];
}

// ---------------------------------------------------------------------------
// LN1 + roll(-4,-4) + window partition. Warp per token.
// ---------------------------------------------------------------------------
__global__ __launch_bounds__(256) void ln1_win_kernel(
    const float* __restrict__ x, const float* __restrict__ gw, const float* __restrict__ bw,
    float* __restrict__ qin_f32, __nv_bfloat16* __restrict__ qin_bf,
    __nv_bfloat16* __restrict__ kvin_bf)
{
    int token = blockIdx.x * 8 + (threadIdx.x >> 5);
    int lane = threadIdx.x & 31;
    int w = token & 255, h = (token >> 8) & 255, d = (token >> 16) & 1, b = token >> 17;

    const float4* row = (const float4*)(x + (size_t)token * 256);
    float4 v0 = row[lane * 2], v1 = row[lane * 2 + 1];
    float s  = v0.x + v0.y + v0.z + v0.w + v1.x + v1.y + v1.z + v1.w;
    float ss = v0.x*v0.x + v0.y*v0.y + v0.z*v0.z + v0.w*v0.w
             + v1.x*v1.x + v1.y*v1.y + v1.z*v1.z + v1.w*v1.w;
    #pragma unroll
    for (int o = 16; o > 0; o >>= 1) {
        s  += __shfl_xor_sync(0xffffffffu, s,  o);
        ss += __shfl_xor_sync(0xffffffffu, ss, o);
    }
    float mean = s * (1.0f / 256.0f);
    float inv  = rsqrtf(ss * (1.0f / 256.0f) - mean * mean + 1e-5f);

    float4 ga = ((const float4*)gw)[lane * 2], gb = ((const float4*)gw)[lane * 2 + 1];
    float4 ba = ((const float4*)bw)[lane * 2], bb = ((const float4*)bw)[lane * 2 + 1];
    float4 o0, o1;
    o0.x = (v0.x - mean) * inv * ga.x + ba.x;
    o0.y = (v0.y - mean) * inv * ga.y + ba.y;
    o0.z = (v0.z - mean) * inv * ga.z + ba.z;
    o0.w = (v0.w - mean) * inv * ga.w + ba.w;
    o1.x = (v1.x - mean) * inv * gb.x + bb.x;
    o1.y = (v1.y - mean) * inv * gb.y + bb.y;
    o1.z = (v1.z - mean) * inv * gb.z + bb.z;
    o1.w = (v1.w - mean) * inv * gb.w + bb.w;

    int hs = (h - 4) & 255, ws = (w - 4) & 255;
    int wi = ((hs >> 3) << 5) | (ws >> 3);
    int n  = ((hs & 7) << 3) | (ws & 7);
    int drow = (((b << 10) | wi) << 6) | n;

    int c0 = lane * 8;
    uint4 bfv;
    bfv.x = packbf(o0.x, o0.y); bfv.y = packbf(o0.z, o0.w);
    bfv.z = packbf(o1.x, o1.y); bfv.w = packbf(o1.z, o1.w);

    int mt = drow >> 7, kt = c0 >> 6, lr = drow & 127, lc = c0 & 63;
    size_t tbase = ((size_t)(mt * 4 + kt)) << 14;
    uint32_t off = SWZ((uint32_t)(lr * 128 + lc * 2));

    if (d == 0) {
        float4* qo = (float4*)(qin_f32 + (size_t)drow * 256);
        qo[lane * 2] = o0; qo[lane * 2 + 1] = o1;
        *(uint4*)((unsigned char*)qin_bf + tbase + off) = bfv;
    } else {
        *(uint4*)((unsigned char*)kvin_bf + tbase + off) = bfv;
    }
}

// ---------------------------------------------------------------------------
// LN2: x1 fp32 -> yn bf16 tiles. Warp per token.
// ---------------------------------------------------------------------------
__global__ __launch_bounds__(256) void ln2_kernel(
    const float* __restrict__ in, const float* __restrict__ gw, const float* __restrict__ bw,
    __nv_bfloat16* __restrict__ out_bf)
{
    int token = blockIdx.x * 8 + (threadIdx.x >> 5);
    int lane = threadIdx.x & 31;
    const float4* row = (const float4*)(in + (size_t)token * 256);
    float4 v0 = row[lane * 2], v1 = row[lane * 2 + 1];
    float s  = v0.x + v0.y + v0.z + v0.w + v1.x + v1.y + v1.z + v1.w;
    float ss = v0.x*v0.x + v0.y*v0.y + v0.z*v0.z + v0.w*v0.w
             + v1.x*v1.x + v1.y*v1.y + v1.z*v1.z + v1.w*v1.w;
    #pragma unroll
    for (int o = 16; o > 0; o >>= 1) {
        s  += __shfl_xor_sync(0xffffffffu, s,  o);
        ss += __shfl_xor_sync(0xffffffffu, ss, o);
    }
    float mean = s * (1.0f / 256.0f);
    float inv  = rsqrtf(ss * (1.0f / 256.0f) - mean * mean + 1e-5f);

    float4 ga = ((const float4*)gw)[lane * 2], gb = ((const float4*)gw)[lane * 2 + 1];
    float4 ba = ((const float4*)bw)[lane * 2], bb = ((const float4*)bw)[lane * 2 + 1];
    float4 o0, o1;
    o0.x = (v0.x - mean) * inv * ga.x + ba.x;
    o0.y = (v0.y - mean) * inv * ga.y + ba.y;
    o0.z = (v0.z - mean) * inv * ga.z + ba.z;
    o0.w = (v0.w - mean) * inv * ga.w + ba.w;
    o1.x = (v1.x - mean) * inv * gb.x + bb.x;
    o1.y = (v1.y - mean) * inv * gb.y + bb.y;
    o1.z = (v1.z - mean) * inv * gb.z + bb.z;
    o1.w = (v1.w - mean) * inv * gb.w + bb.w;

    int c0 = lane * 8;
    uint4 bfv;
    bfv.x = packbf(o0.x, o0.y); bfv.y = packbf(o0.z, o0.w);
    bfv.z = packbf(o1.x, o1.y); bfv.w = packbf(o1.z, o1.w);
    int mt = token >> 7, kt = c0 >> 6, lr = token & 127, lc = c0 & 63;
    size_t tbase = ((size_t)(mt * 4 + kt)) << 14;
    uint32_t off = SWZ((uint32_t)(lr * 128 + lc * 2));
    *(uint4*)((unsigned char*)out_bf + tbase + off) = bfv;
}

// ---------------------------------------------------------------------------
// HMMA bf16 GEMM v3: CTA 128x128, 4 warps (2Mx2N), warp tile 64x64.
// 8 LDSM.x4 per 32 MMA per k-step (4 mma/ldsm). 3-stage cp.async.
// ---------------------------------------------------------------------------
#define GEMM_SMEM (98304)
template<int MODE>
__global__ __launch_bounds__(128, 2) void gemm_mma(
    const __nv_bfloat16* __restrict__ A, const __nv_bfloat16* __restrict__ B,
    const float* __restrict__ bias, void* __restrict__ Cout, int K,
    const float* __restrict__ aux1, const float* __restrict__ aux2)
{
    extern __shared__ __align__(1024) unsigned char dsm[];
    uint32_t sbase = smem_u32(dsm);
    uint32_t stA[3] = { sbase, sbase + 32768, sbase + 65536 };
    uint32_t stB[3] = { sbase + 16384, sbase + 49152, sbase + 81920 };

    int tid = threadIdx.x, wid = tid >> 5, lane = tid & 31;
    int KC = K >> 6;
    const unsigned char* Ab = (const unsigned char*)A + (((size_t)blockIdx.y * KC) << 14);
    const unsigned char* Bb = (const unsigned char*)B + (((size_t)blockIdx.x * KC) << 14);

    auto load_chunk = [&](int kc, int st) {
        const unsigned char* ga = Ab + ((size_t)kc << 14);
        const unsigned char* gb = Bb + ((size_t)kc << 14);
        #pragma unroll
        for (int i = 0; i < 8; i++) {
            int o = tid * 16 + i * 2048;
            cp16(stA[st] + o, ga + o);
            cp16(stB[st] + o, gb + o);
        }
        cp_commit();
    };

    int wm = wid & 1, wn = wid >> 1;
    int am0 = wm * 64, bn0 = wn * 64;
    int row_off = ((lane >> 3) & 1) * 8 + (lane & 7);
    int colbit  = ((lane >> 4) & 1) * 16;
    uint32_t xr = (uint32_t)((lane & 7) << 4);
    uint32_t aro[4], bro[4];
    #pragma unroll
    for (int ma = 0; ma < 4; ma++) aro[ma] = (uint32_t)((am0 + ma * 16 + row_off) * 128);
    #pragma unroll
    for (int nb = 0; nb < 4; nb++) bro[nb] = (uint32_t)((bn0 + nb * 16 + row_off) * 128);

    float acc[4][8][4];
    #pragma unroll
    for (int ma = 0; ma < 4; ma++)
        #pragma unroll
        for (int na = 0; na < 8; na++)
            #pragma unroll
            for (int i = 0; i < 4; i++) acc[ma][na][i] = 0.f;

    load_chunk(0, 0);
    load_chunk(1, 1);
    int s = 0, ls = 2;
    for (int kc = 0; kc < KC; kc++) {
        if (kc == KC - 1) cp_wait<0>(); else cp_wait<1>();
        __syncthreads();
        if (kc + 2 < KC) {
            load_chunk(kc + 2, ls);
            if (++ls == 3) ls = 0;
        }
        #pragma unroll
        for (int ks = 0; ks < 4; ks++) {
            uint32_t cbyte = (uint32_t)(ks * 32 + colbit) ^ xr;
            uint32_t a[4][4], b[4][4];
            #pragma unroll
            for (int ma = 0; ma < 4; ma++)
                ldm_x4(a[ma][0], a[ma][1], a[ma][2], a[ma][3], stA[s] + aro[ma] + cbyte);
            #pragma unroll
            for (int nb = 0; nb < 4; nb++)
                ldm_x4(b[nb][0], b[nb][1], b[nb][2], b[nb][3], stB[s] + bro[nb] + cbyte);
            #pragma unroll
            for (int ma = 0; ma < 4; ma++)
                #pragma unroll
                for (int na = 0; na < 8; na++)
                    mma_bf16(acc[ma][na], a[ma], b[na >> 1][na & 1], b[na >> 1][2 + (na & 1)]);
        }
        if (++s == 3) s = 0;
    }

    int lm = lane >> 2, ln = (lane & 3) * 2;
    int m_cta = blockIdx.y * 128;
    int n_cta = blockIdx.x * 128;

    float2 bias2[8];
    #pragma unroll
    for (int na = 0; na < 8; na++)
        bias2[na] = *(const float2*)(bias + n_cta + bn0 + na * 8 + ln);

    #pragma unroll
    for (int ma = 0; ma < 4; ma++) {
        #pragma unroll
        for (int half = 0; half < 2; half++) {
            int r = m_cta + am0 + ma * 16 + lm + half * 8;
            size_t drow = 0; const float* shortcut = nullptr;
            if (MODE == 2) {
                int wdx = r >> 6, n = r & 63;
                int b = wdx >> 10, wi = wdx & 1023;
                int hh = ((wi >> 5) << 3) + (n >> 3);
                int ww = ((wi & 31) << 3) + (n & 7);
                hh = (hh + 4) & 255; ww = (ww + 4) & 255;
                drow = ((size_t)b * 256 + hh) * 256 + ww;
                shortcut = aux2 + ((((size_t)b * 2) * 256 + hh) * 256 + ww) * 256;
            }
            #pragma unroll
            for (int na = 0; na < 8; na++) {
                int c = n_cta + bn0 + na * 8 + ln;
                float v0 = acc[ma][na][half * 2]     + bias2[na].x;
                float v1 = acc[ma][na][half * 2 + 1] + bias2[na].y;
                if (MODE == 0) {
                    v0 *= 0.17677669529663687f; v1 *= 0.17677669529663687f;
                    *(uint32_t*)((__nv_bfloat16*)Cout + (size_t)r * 256 + c) = packbf(v0, v1);
                } else if (MODE == 1) {
                    *(uint32_t*)((__nv_bfloat16*)Cout + (size_t)r * 512 + c) = packbf(v0, v1);
                } else if (MODE == 2) {
                    float2 av = *(const float2*)(aux1 + (size_t)r * 256 + c);
                    float2 sv = *(const float2*)(shortcut + c);
                    *(float2*)((float*)Cout + drow * 256 + c) =
                        make_float2(v0 + av.x + sv.x, v1 + av.y + sv.y);
                } else if (MODE == 3) {
                    v0 = 0.5f * v0 * (1.0f + erff(v0 * 0.70710678118654752f));
                    v1 = 0.5f * v1 * (1.0f + erff(v1 * 0.70710678118654752f));
                    int mt = r >> 7, lr = r & 127;
                    int kt = c >> 6, lc = c & 63;
                    size_t tbase = ((size_t)(mt * 16 + kt)) << 14;
                    uint32_t off = SWZ((uint32_t)(lr * 128 + lc * 2));
                    *(uint32_t*)((unsigned char*)Cout + tbase + off) = packbf(v0, v1);
                } else { // MODE 4
                    float2 av = *(const float2*)(aux1 + (size_t)r * 256 + c);
                    *(float2*)((float*)Cout + (size_t)r * 256 + c) =
                        make_float2(v0 + av.x, v1 + av.y);
                }
            }
        }
    }
}

// ---------------------------------------------------------------------------
// Tensor-core attention: 1 CTA (256 thr, 8 warps) per window, warp = head.
// ---------------------------------------------------------------------------
#define ATT_SMEM (96 * 1024)
__global__ __launch_bounds__(256) void attn_mma_kernel(
    const __nv_bfloat16* __restrict__ q, const __nv_bfloat16* __restrict__ kv,
    __nv_bfloat16* __restrict__ att_bf,
    const float* __restrict__ mask, const float* __restrict__ biasf)
{
    extern __shared__ __align__(128) unsigned char dsm[];
    uint32_t sQ  = smem_u32(dsm);      // 64 rows x 32 chunks x 16B = 32KB
    uint32_t sKV = sQ + 32768;         // 64 rows x 64 chunks x 16B = 64KB

    int w = blockIdx.x;
    int tid = threadIdx.x, h = tid >> 5, lane = tid & 31;

    const unsigned char* qg  = (const unsigned char*)(q  + (size_t)w * 64 * 256);
    const unsigned char* kvg = (const unsigned char*)(kv + (size_t)w * 64 * 512);
    #pragma unroll
    for (int i = 0; i < 8; i++) {
        int g = tid + i * 256;
        int r = g >> 5, c = g & 31;
        cp16(sQ + (r * 32 + (c ^ (r & 7))) * 16, qg + (size_t)r * 512 + c * 16);
    }
    #pragma unroll
    for (int i = 0; i < 16; i++) {
        int g = tid + i * 256;
        int r = g >> 6, c = g & 63;
        cp16(sKV + (r * 64 + (c ^ (r & 7))) * 16, kvg + (size_t)r * 1024 + c * 16);
    }
    cp_commit(); cp_wait<0>();
    __syncthreads();

    int rsel = (lane & 7) + ((lane & 8) ? 8 : 0);
    int csel = (lane >> 4) & 1;

    uint32_t vb[4][4][2];
    #pragma unroll
    for (int kt = 0; kt < 4; kt++) {
        #pragma unroll
        for (int half = 0; half < 2; half++) {
            int vr = kt * 16 + rsel;
            int ch = 32 + h * 4 + half * 2 + csel;
            uint32_t r0, r1, r2, r3;
            ldm_x4t(r0, r1, r2, r3, sKV + (vr * 64 + (ch ^ (vr & 7))) * 16);
            vb[kt][half * 2 + 0][0] = r0; vb[kt][half * 2 + 0][1] = r1;
            vb[kt][half * 2 + 1][0] = r2; vb[kt][half * 2 + 1][1] = r3;
        }
    }

    const float* mbase = mask + (size_t)(w & 1023) * 4096;
    const float* bh = biasf + h * 4096;
    int ln2 = (lane & 3) * 2;

    #pragma unroll
    for (int mt = 0; mt < 4; mt++) {
        uint32_t qf[2][4];
        int qr = mt * 16 + rsel;
        #pragma unroll
        for (int t = 0; t < 2; t++) {
            int ch = h * 4 + t * 2 + csel;
            ldm_x4(qf[t][0], qf[t][1], qf[t][2], qf[t][3],
                   sQ + (qr * 32 + (ch ^ (qr & 7))) * 16);
        }
        float S[8][4];
        #pragma unroll
        for (int nt = 0; nt < 8; nt++)
            #pragma unroll
            for (int i = 0; i < 4; i++) S[nt][i] = 0.f;
        #pragma unroll
        for (int nt = 0; nt < 4; nt++) {
            uint32_t kb[2][4];
            int kr = nt * 16 + rsel;
            #pragma unroll
            for (int t = 0; t < 2; t++) {
                int ch = h * 4 + t * 2 + csel;
                ldm_x4(kb[t][0], kb[t][1], kb[t][2], kb[t][3],
                       sKV + (kr * 64 + (ch ^ (kr & 7))) * 16);
            }
            #pragma unroll
            for (int j = 0; j < 2; j++) {
                mma_bf16(S[2 * nt + j], qf[0], kb[0][j], kb[0][2 + j]);
                mma_bf16(S[2 * nt + j], qf[1], kb[1][j], kb[1][2 + j]);
            }
        }
        int r1 = mt * 16 + (lane >> 2), r2 = r1 + 8;
        #pragma unroll
        for (int nt = 0; nt < 8; nt++) {
            int cb = nt * 8 + ln2;
            float2 mk1 = *(const float2*)(mbase + r1 * 64 + cb);
            float2 mk2 = *(const float2*)(mbase + r2 * 64 + cb);
            float2 b1v = *(const float2*)(bh + r1 * 64 + cb);
            float2 b2v = *(const float2*)(bh + r2 * 64 + cb);
            S[nt][0] += mk1.x + b1v.x; S[nt][1] += mk1.y + b1v.y;
            S[nt][2] += mk2.x + b2v.x; S[nt][3] += mk2.y + b2v.y;
        }
        float mx1 = -1e30f, mx2 = -1e30f;
        #pragma unroll
        for (int nt = 0; nt < 8; nt++) {
            mx1 = fmaxf(mx1, fmaxf(S[nt][0], S[nt][1]));
            mx2 = fmaxf(mx2, fmaxf(S[nt][2], S[nt][3]));
        }
        mx1 = fmaxf(mx1, __shfl_xor_sync(0xffffffffu, mx1, 1));
        mx1 = fmaxf(mx1, __shfl_xor_sync(0xffffffffu, mx1, 2));
        mx2 = fmaxf(mx2, __shfl_xor_sync(0xffffffffu, mx2, 1));
        mx2 = fmaxf(mx2, __shfl_xor_sync(0xffffffffu, mx2, 2));
        float s1 = 0.f, s2 = 0.f;
        #pragma unroll
        for (int nt = 0; nt < 8; nt++) {
            S[nt][0] = __expf(S[nt][0] - mx1); s1 += S[nt][0];
            S[nt][1] = __expf(S[nt][1] - mx1); s1 += S[nt][1];
            S[nt][2] = __expf(S[nt][2] - mx2); s2 += S[nt][2];
            S[nt][3] = __expf(S[nt][3] - mx2); s2 += S[nt][3];
        }
        s1 += __shfl_xor_sync(0xffffffffu, s1, 1);
        s1 += __shfl_xor_sync(0xffffffffu, s1, 2);
        s2 += __shfl_xor_sync(0xffffffffu, s2, 1);
        s2 += __shfl_xor_sync(0xffffffffu, s2, 2);
        float i1 = 1.0f / s1, i2 = 1.0f / s2;
        uint32_t pa[4][4];
        #pragma unroll
        for (int kt = 0; kt < 4; kt++) {
            pa[kt][0] = packbf(S[2*kt][0]   * i1, S[2*kt][1]   * i1);
            pa[kt][1] = packbf(S[2*kt][2]   * i2, S[2*kt][3]   * i2);
            pa[kt][2] = packbf(S[2*kt+1][0] * i1, S[2*kt+1][1] * i1);
            pa[kt][3] = packbf(S[2*kt+1][2] * i2, S[2*kt+1][3] * i2);
        }
        float of[4][4];
        #pragma unroll
        for (int nd = 0; nd < 4; nd++)
            #pragma unroll
            for (int i = 0; i < 4; i++) of[nd][i] = 0.f;
        #pragma unroll
        for (int kt = 0; kt < 4; kt++)
            #pragma unroll
            for (int nd = 0; nd < 4; nd++)
                mma_bf16(of[nd], pa[kt], vb[kt][nd][0], vb[kt][nd][1]);
        int rg1 = (w << 6) + r1, rg2 = (w << 6) + r2;
        int mtg = rg1 >> 7;
        int lr1 = rg1 & 127, lr2 = rg2 & 127;
        #pragma unroll
        for (int nd = 0; nd < 4; nd++) {
            int c = h * 32 + nd * 8 + ln2;
            int ktg = c >> 6, lc = c & 63;
            size_t tbase = ((size_t)(mtg * 4 + ktg)) << 14;
            *(uint32_t*)((unsigned char*)att_bf + tbase + SWZ((uint32_t)(lr1 * 128 + lc * 2)))
                = packbf(of[nd][0], of[nd][1]);
            *(uint32_t*)((unsigned char*)att_bf + tbase + SWZ((uint32_t)(lr2 * 128 + lc * 2)))
                = packbf(of[nd][2], of[nd][3]);
        }
    }
}

// ---------------------------------------------------------------------------
extern "C" void kernel_launch(void* const* d_in, const int* in_sizes, int n_in,
                              void* d_out, int out_size)
{
    const float* x          = (const float*)d_in[0];
    const float* mask       = (const float*)d_in[1];
    const float* g1         = (const float*)d_in[2];
    const float* b1         = (const float*)d_in[3];
    const float* qw         = (const float*)d_in[4];
    const float* qb         = (const float*)d_in[5];
    const float* kvw        = (const float*)d_in[6];
    const float* kvb        = (const float*)d_in[7];
    const float* pw         = (const float*)d_in[8];
    const float* pb         = (const float*)d_in[9];
    const float* bias_table = (const float*)d_in[10];
    const float* g2         = (const float*)d_in[11];
    const float* b2         = (const float*)d_in[12];
    const float* w1         = (const float*)d_in[13];
    const float* bi1        = (const float*)d_in[14];
    const float* w2         = (const float*)d_in[15];
    const float* bi2        = (const float*)d_in[16];
    float* out = (float*)d_out;

    unsigned char* pool = nullptr;
    cudaGetSymbolAddress((void**)&pool, g_pool);

    float*          qin_f32 = (float*)(pool + OFF_QIN_F32);
    __nv_bfloat16*  q_bf    = (__nv_bfloat16*)(pool + OFF_Q_BF);
    __nv_bfloat16*  kv_bf   = (__nv_bfloat16*)(pool + OFF_KV_BF);
    __nv_bfloat16*  qin_bf  = (__nv_bfloat16*)(pool + OFF_QIN_BF);
    __nv_bfloat16*  kvin_bf = (__nv_bfloat16*)(pool + OFF_KVIN_BF);
    __nv_bfloat16*  att_bf  = (__nv_bfloat16*)(pool + OFF_ATT_BF);
    float*          x1      = (float*)(pool + OFF_X1_F32);
    __nv_bfloat16*  wq_bf   = (__nv_bfloat16*)(pool + OFF_WQ_BF);
    __nv_bfloat16*  wkv_bf  = (__nv_bfloat16*)(pool + OFF_WKV_BF);
    __nv_bfloat16*  wp_bf   = (__nv_bfloat16*)(pool + OFF_W_P_BF);
    __nv_bfloat16*  w1_bf   = (__nv_bfloat16*)(pool + OFF_W1_BF);
    __nv_bfloat16*  w2_bf   = (__nv_bfloat16*)(pool + OFF_W2_BF);
    float*          biasf   = (float*)(pool + OFF_BIASF);
    __nv_bfloat16*  hid_bf  = (__nv_bfloat16*)(pool + OFF_HID_BF);
    __nv_bfloat16*  yn_bf   = (__nv_bfloat16*)(pool + OFF_YN_BF);

    cudaFuncSetAttribute(gemm_mma<0>, cudaFuncAttributeMaxDynamicSharedMemorySize, GEMM_SMEM);
    cudaFuncSetAttribute(gemm_mma<1>, cudaFuncAttributeMaxDynamicSharedMemorySize, GEMM_SMEM);
    cudaFuncSetAttribute(gemm_mma<2>, cudaFuncAttributeMaxDynamicSharedMemorySize, GEMM_SMEM);
    cudaFuncSetAttribute(gemm_mma<3>, cudaFuncAttributeMaxDynamicSharedMemorySize, GEMM_SMEM);
    cudaFuncSetAttribute(gemm_mma<4>, cudaFuncAttributeMaxDynamicSharedMemorySize, GEMM_SMEM);
    cudaFuncSetAttribute(attn_mma_kernel, cudaFuncAttributeMaxDynamicSharedMemorySize, ATT_SMEM);

    // 0,1. merged weight conversion + bias expansion
    convall_kernel<<<384, 256>>>(qw, kvw, pw, w1, w2, wq_bf, wkv_bf, wp_bf, w1_bf, w2_bf);
    biasx_kernel<<<64, 64>>>(bias_table, biasf);

    // 2. LN1 + shift + window partition
    ln1_win_kernel<<<(2 * 2 * 256 * 256) / 8, 256>>>(x, g1, b1, qin_f32, qin_bf, kvin_bf);

    // 3. Q GEMM -> bf16 row-major (scaled by 1/sqrt(32))
    gemm_mma<0><<<dim3(2, 1024), 128, GEMM_SMEM>>>(qin_bf, wq_bf, qb, q_bf, 256, nullptr, nullptr);

    // 4. KV GEMM -> bf16 row-major
    gemm_mma<1><<<dim3(4, 1024), 128, GEMM_SMEM>>>(kvin_bf, wkv_bf, kvb, kv_bf, 256, nullptr, nullptr);

    // 5. tensor-core attention -> att bf16 tiles  (ncu capture lands here)
    attn_mma_kernel<<<2048, 256, ATT_SMEM>>>(q_bf, kv_bf, att_bf, mask, biasf);

    // 6. proj + residual(q_in fp32) + shortcut + inverse-roll scatter -> x1 fp32
    gemm_mma<2><<<dim3(2, 1024), 128, GEMM_SMEM>>>(att_bf, wp_bf, pb, x1, 256, qin_f32, x);

    // 7. LN2 -> yn bf16 tiles
    ln2_kernel<<<ROWS / 8, 256>>>(x1, g2, b2, yn_bf);

    // 8. MLP1 + gelu -> hid bf16 tiles
    gemm_mma<3><<<dim3(8, 1024), 128, GEMM_SMEM>>>(yn_bf, w1_bf, bi1, hid_bf, 256, nullptr, nullptr);

    // 9. MLP2 + residual(x1) -> out fp32
    gemm_mma<4><<<dim3(2, 1024), 128, GEMM_SMEM>>>(hid_bf, w2_bf, bi2, out, 1024, x1, nullptr);
}

// round 11
// speedup vs baseline: 1.0235x; 1.0235x over previous
#include <cuda_runtime.h>
#include <cuda_fp16.h>
#include <math.h>
#include <stdint.h>

// ---------------------------------------------------------------------------
#define ROWS 131072        // B*H*W tokens (= 2048 windows * 64)
#define HID  1024
#define MB   ((size_t)1024 * 1024)

#define POOL_BYTES ((size_t)836 * MB)
__device__ __align__(1024) unsigned char g_pool[POOL_BYTES];

#define OFF_QIN_F32  ((size_t)0)
#define OFF_Q_BF     ((size_t)128 * MB)
#define OFF_KV_BF    ((size_t)256 * MB)
#define OFF_QIN_BF   ((size_t)512 * MB)
#define OFF_KVIN_BF  ((size_t)576 * MB)
#define OFF_ATT_BF   ((size_t)640 * MB)
#define OFF_X1_F32   ((size_t)704 * MB)
#define OFF_WQ_BF    ((size_t)832 * MB)
#define OFF_WKV_BF   (OFF_WQ_BF  + 256 * 256 * 2)
#define OFF_W_P_BF   (OFF_WKV_BF + 512 * 256 * 2)
#define OFF_W1_BF    (OFF_W_P_BF + 256 * 256 * 2)
#define OFF_W2_BF    (OFF_W1_BF  + 1024 * 256 * 2)
#define OFF_BIASF    (OFF_W2_BF  + 1024 * 256 * 2)   // [8][64][64] f32 = 128KB
#define OFF_HID_BF   ((size_t)0)
#define OFF_YN_BF    ((size_t)256 * MB)

// SW128 swizzle for 128B-row fp16 tiles
#define SWZ(o) ((o) ^ (((o) >> 3) & 0x70))

// ---------------------------------------------------------------------------
// PTX helpers (baseline sm_100-safe)
// ---------------------------------------------------------------------------
__device__ __forceinline__ uint32_t smem_u32(const void* p) {
    uint32_t a;
    asm("{ .reg .u64 t; cvta.to.shared.u64 t, %1; cvt.u32.u64 %0, t; }" : "=r"(a) : "l"(p));
    return a;
}
__device__ __forceinline__ void cp16(uint32_t s, const void* g) {
    asm volatile("cp.async.cg.shared.global [%0], [%1], 16;" :: "r"(s), "l"(g) : "memory");
}
__device__ __forceinline__ void cp_commit() { asm volatile("cp.async.commit_group;" ::: "memory"); }
template<int N> __device__ __forceinline__ void cp_wait() {
    asm volatile("cp.async.wait_group %0;" :: "n"(N) : "memory");
}
__device__ __forceinline__ void ldm_x4(uint32_t& r0, uint32_t& r1, uint32_t& r2, uint32_t& r3, uint32_t addr) {
    asm volatile("ldmatrix.sync.aligned.m8n8.x4.shared.b16 {%0,%1,%2,%3}, [%4];"
                 : "=r"(r0), "=r"(r1), "=r"(r2), "=r"(r3) : "r"(addr));
}
__device__ __forceinline__ void ldm_x4t(uint32_t& r0, uint32_t& r1, uint32_t& r2, uint32_t& r3, uint32_t addr) {
    asm volatile("ldmatrix.sync.aligned.m8n8.x4.trans.shared.b16 {%0,%1,%2,%3}, [%4];"
                 : "=r"(r0), "=r"(r1), "=r"(r2), "=r"(r3) : "r"(addr));
}
// fp16 inputs, fp16 accumulate (2 C regs) -- the rate experiment
__device__ __forceinline__ void mma_h16(uint32_t* c, const uint32_t* a, uint32_t b0, uint32_t b1) {
    asm volatile(
        "mma.sync.aligned.m16n8k16.row.col.f16.f16.f16.f16 "
        "{%0,%1}, {%2,%3,%4,%5}, {%6,%7}, {%0,%1};"
        : "+r"(c[0]), "+r"(c[1])
        : "r"(a[0]), "r"(a[1]), "r"(a[2]), "r"(a[3]), "r"(b0), "r"(b1));
}
// fp16 inputs, fp32 accumulate (attention)
__device__ __forceinline__ void mma_hf32(float* c, const uint32_t* a, uint32_t b0, uint32_t b1) {
    asm volatile(
        "mma.sync.aligned.m16n8k16.row.col.f32.f16.f16.f32 "
        "{%0,%1,%2,%3}, {%4,%5,%6,%7}, {%8,%9}, {%0,%1,%2,%3};"
        : "+f"(c[0]), "+f"(c[1]), "+f"(c[2]), "+f"(c[3])
        : "r"(a[0]), "r"(a[1]), "r"(a[2]), "r"(a[3]), "r"(b0), "r"(b1));
}
__device__ __forceinline__ uint32_t packh(float a, float b) {
    __half2 p = __floats2half2_rn(a, b);
    return *(uint32_t*)&p;
}
__device__ __forceinline__ float2 unp2(uint32_t u) {
    return __half22float2(*(__half2*)&u);
}

// ---------------------------------------------------------------------------
// Merged weight conversion: all 5 weights in one launch (fp32 -> fp16 tiles).
// ---------------------------------------------------------------------------
__global__ __launch_bounds__(256) void convall_kernel(
    const float* __restrict__ qw, const float* __restrict__ kvw,
    const float* __restrict__ pw, const float* __restrict__ w1,
    const float* __restrict__ w2,
    __half* __restrict__ dq, __half* __restrict__ dkv,
    __half* __restrict__ dp, __half* __restrict__ dw1,
    __half* __restrict__ dw2)
{
    int blk = blockIdx.x;
    const float* src; __half* dst; int K, base;
    if      (blk < 32)  { src = qw;  dst = dq;  K = 256;  base = 0;   }
    else if (blk < 96)  { src = kvw; dst = dkv; K = 256;  base = 32;  }
    else if (blk < 128) { src = pw;  dst = dp;  K = 256;  base = 96;  }
    else if (blk < 256) { src = w1;  dst = dw1; K = 256;  base = 128; }
    else                { src = w2;  dst = dw2; K = 1024; base = 256; }
    int gid = (blk - base) * 256 + threadIdx.x;
    int kdiv8 = K >> 3;
    int r  = gid / kdiv8;
    int c0 = (gid - r * kdiv8) << 3;
    const float4* s = (const float4*)(src + (size_t)r * K + c0);
    float4 f0 = s[0], f1 = s[1];
    uint4 v;
    v.x = packh(f0.x, f0.y); v.y = packh(f0.z, f0.w);
    v.z = packh(f1.x, f1.y); v.w = packh(f1.z, f1.w);
    int mt = r >> 7, kt = c0 >> 6, lr = r & 127, lc = c0 & 63;
    size_t tbase = ((size_t)(mt * (K >> 6) + kt)) << 14;
    uint32_t off = SWZ((uint32_t)(lr * 128 + lc * 2));
    *(uint4*)((unsigned char*)dst + tbase + off) = v;
}

// Expand rel-pos bias table -> biasf[8][64][64]
__global__ __launch_bounds__(64) void biasx_kernel(
    const float* __restrict__ btab, float* __restrict__ biasf)
{
    int n = blockIdx.x, m = threadIdx.x;
    int idx = (((n >> 3) - (m >> 3) + 7) * 15 + ((n & 7) - (m & 7) + 7)) * 8;
    #pragma unroll
    for (int h = 0; h < 8; h++)
        biasf[h * 4096 + n * 64 + m] = btab[idx + h];
}

// ---------------------------------------------------------------------------
// LN1 + roll(-4,-4) + window partition. Warp per token.
// ---------------------------------------------------------------------------
__global__ __launch_bounds__(256) void ln1_win_kernel(
    const float* __restrict__ x, const float* __restrict__ gw, const float* __restrict__ bw,
    float* __restrict__ qin_f32, __half* __restrict__ qin_bf,
    __half* __restrict__ kvin_bf)
{
    int token = blockIdx.x * 8 + (threadIdx.x >> 5);
    int lane = threadIdx.x & 31;
    int w = token & 255, h = (token >> 8) & 255, d = (token >> 16) & 1, b = token >> 17;

    const float4* row = (const float4*)(x + (size_t)token * 256);
    float4 v0 = row[lane * 2], v1 = row[lane * 2 + 1];
    float s  = v0.x + v0.y + v0.z + v0.w + v1.x + v1.y + v1.z + v1.w;
    float ss = v0.x*v0.x + v0.y*v0.y + v0.z*v0.z + v0.w*v0.w
             + v1.x*v1.x + v1.y*v1.y + v1.z*v1.z + v1.w*v1.w;
    #pragma unroll
    for (int o = 16; o > 0; o >>= 1) {
        s  += __shfl_xor_sync(0xffffffffu, s,  o);
        ss += __shfl_xor_sync(0xffffffffu, ss, o);
    }
    float mean = s * (1.0f / 256.0f);
    float inv  = rsqrtf(ss * (1.0f / 256.0f) - mean * mean + 1e-5f);

    float4 ga = ((const float4*)gw)[lane * 2], gb = ((const float4*)gw)[lane * 2 + 1];
    float4 ba = ((const float4*)bw)[lane * 2], bb = ((const float4*)bw)[lane * 2 + 1];
    float4 o0, o1;
    o0.x = (v0.x - mean) * inv * ga.x + ba.x;
    o0.y = (v0.y - mean) * inv * ga.y + ba.y;
    o0.z = (v0.z - mean) * inv * ga.z + ba.z;
    o0.w = (v0.w - mean) * inv * ga.w + ba.w;
    o1.x = (v1.x - mean) * inv * gb.x + bb.x;
    o1.y = (v1.y - mean) * inv * gb.y + bb.y;
    o1.z = (v1.z - mean) * inv * gb.z + bb.z;
    o1.w = (v1.w - mean) * inv * gb.w + bb.w;

    int hs = (h - 4) & 255, ws = (w - 4) & 255;
    int wi = ((hs >> 3) << 5) | (ws >> 3);
    int n  = ((hs & 7) << 3) | (ws & 7);
    int drow = (((b << 10) | wi) << 6) | n;

    int c0 = lane * 8;
    uint4 bfv;
    bfv.x = packh(o0.x, o0.y); bfv.y = packh(o0.z, o0.w);
    bfv.z = packh(o1.x, o1.y); bfv.w = packh(o1.z, o1.w);

    int mt = drow >> 7, kt = c0 >> 6, lr = drow & 127, lc = c0 & 63;
    size_t tbase = ((size_t)(mt * 4 + kt)) << 14;
    uint32_t off = SWZ((uint32_t)(lr * 128 + lc * 2));

    if (d == 0) {
        float4* qo = (float4*)(qin_f32 + (size_t)drow * 256);
        qo[lane * 2] = o0; qo[lane * 2 + 1] = o1;
        *(uint4*)((unsigned char*)qin_bf + tbase + off) = bfv;
    } else {
        *(uint4*)((unsigned char*)kvin_bf + tbase + off) = bfv;
    }
}

// ---------------------------------------------------------------------------
// LN2: x1 fp32 -> yn fp16 tiles. Warp per token.
// ---------------------------------------------------------------------------
__global__ __launch_bounds__(256) void ln2_kernel(
    const float* __restrict__ in, const float* __restrict__ gw, const float* __restrict__ bw,
    __half* __restrict__ out_bf)
{
    int token = blockIdx.x * 8 + (threadIdx.x >> 5);
    int lane = threadIdx.x & 31;
    const float4* row = (const float4*)(in + (size_t)token * 256);
    float4 v0 = row[lane * 2], v1 = row[lane * 2 + 1];
    float s  = v0.x + v0.y + v0.z + v0.w + v1.x + v1.y + v1.z + v1.w;
    float ss = v0.x*v0.x + v0.y*v0.y + v0.z*v0.z + v0.w*v0.w
             + v1.x*v1.x + v1.y*v1.y + v1.z*v1.z + v1.w*v1.w;
    #pragma unroll
    for (int o = 16; o > 0; o >>= 1) {
        s  += __shfl_xor_sync(0xffffffffu, s,  o);
        ss += __shfl_xor_sync(0xffffffffu, ss, o);
    }
    float mean = s * (1.0f / 256.0f);
    float inv  = rsqrtf(ss * (1.0f / 256.0f) - mean * mean + 1e-5f);

    float4 ga = ((const float4*)gw)[lane * 2], gb = ((const float4*)gw)[lane * 2 + 1];
    float4 ba = ((const float4*)bw)[lane * 2], bb = ((const float4*)bw)[lane * 2 + 1];
    float4 o0, o1;
    o0.x = (v0.x - mean) * inv * ga.x + ba.x;
    o0.y = (v0.y - mean) * inv * ga.y + ba.y;
    o0.z = (v0.z - mean) * inv * ga.z + ba.z;
    o0.w = (v0.w - mean) * inv * ga.w + ba.w;
    o1.x = (v1.x - mean) * inv * gb.x + bb.x;
    o1.y = (v1.y - mean) * inv * gb.y + bb.y;
    o1.z = (v1.z - mean) * inv * gb.z + bb.z;
    o1.w = (v1.w - mean) * inv * gb.w + bb.w;

    int c0 = lane * 8;
    uint4 bfv;
    bfv.x = packh(o0.x, o0.y); bfv.y = packh(o0.z, o0.w);
    bfv.z = packh(o1.x, o1.y); bfv.w = packh(o1.z, o1.w);
    int mt = token >> 7, kt = c0 >> 6, lr = token & 127, lc = c0 & 63;
    size_t tbase = ((size_t)(mt * 4 + kt)) << 14;
    uint32_t off = SWZ((uint32_t)(lr * 128 + lc * 2));
    *(uint4*)((unsigned char*)out_bf + tbase + off) = bfv;
}

// ---------------------------------------------------------------------------
// HMMA fp16 GEMM (fp16 accumulate): CTA 128x128, 4 warps (2Mx2N), warp 64x64.
// 3-stage cp.async pipeline.
// ---------------------------------------------------------------------------
#define GEMM_SMEM (98304)
template<int MODE>
__global__ __launch_bounds__(128, 2) void gemm_mma(
    const __half* __restrict__ A, const __half* __restrict__ B,
    const float* __restrict__ bias, void* __restrict__ Cout, int K,
    const float* __restrict__ aux1, const float* __restrict__ aux2)
{
    extern __shared__ __align__(1024) unsigned char dsm[];
    uint32_t sbase = smem_u32(dsm);
    uint32_t stA[3] = { sbase, sbase + 32768, sbase + 65536 };
    uint32_t stB[3] = { sbase + 16384, sbase + 49152, sbase + 81920 };

    int tid = threadIdx.x, wid = tid >> 5, lane = tid & 31;
    int KC = K >> 6;
    const unsigned char* Ab = (const unsigned char*)A + (((size_t)blockIdx.y * KC) << 14);
    const unsigned char* Bb = (const unsigned char*)B + (((size_t)blockIdx.x * KC) << 14);

    auto load_chunk = [&](int kc, int st) {
        const unsigned char* ga = Ab + ((size_t)kc << 14);
        const unsigned char* gb = Bb + ((size_t)kc << 14);
        #pragma unroll
        for (int i = 0; i < 8; i++) {
            int o = tid * 16 + i * 2048;
            cp16(stA[st] + o, ga + o);
            cp16(stB[st] + o, gb + o);
        }
        cp_commit();
    };

    int wm = wid & 1, wn = wid >> 1;
    int am0 = wm * 64, bn0 = wn * 64;
    int row_off = ((lane >> 3) & 1) * 8 + (lane & 7);
    int colbit  = ((lane >> 4) & 1) * 16;
    uint32_t xr = (uint32_t)((lane & 7) << 4);
    uint32_t aro[4], bro[4];
    #pragma unroll
    for (int ma = 0; ma < 4; ma++) aro[ma] = (uint32_t)((am0 + ma * 16 + row_off) * 128);
    #pragma unroll
    for (int nb = 0; nb < 4; nb++) bro[nb] = (uint32_t)((bn0 + nb * 16 + row_off) * 128);

    uint32_t acc[4][8][2];
    #pragma unroll
    for (int ma = 0; ma < 4; ma++)
        #pragma unroll
        for (int na = 0; na < 8; na++) { acc[ma][na][0] = 0u; acc[ma][na][1] = 0u; }

    load_chunk(0, 0);
    load_chunk(1, 1);
    int s = 0, ls = 2;
    for (int kc = 0; kc < KC; kc++) {
        if (kc == KC - 1) cp_wait<0>(); else cp_wait<1>();
        __syncthreads();
        if (kc + 2 < KC) {
            load_chunk(kc + 2, ls);
            if (++ls == 3) ls = 0;
        }
        #pragma unroll
        for (int ks = 0; ks < 4; ks++) {
            uint32_t cbyte = (uint32_t)(ks * 32 + colbit) ^ xr;
            uint32_t a[4][4], b[4][4];
            #pragma unroll
            for (int ma = 0; ma < 4; ma++)
                ldm_x4(a[ma][0], a[ma][1], a[ma][2], a[ma][3], stA[s] + aro[ma] + cbyte);
            #pragma unroll
            for (int nb = 0; nb < 4; nb++)
                ldm_x4(b[nb][0], b[nb][1], b[nb][2], b[nb][3], stB[s] + bro[nb] + cbyte);
            #pragma unroll
            for (int ma = 0; ma < 4; ma++)
                #pragma unroll
                for (int na = 0; na < 8; na++)
                    mma_h16(acc[ma][na], a[ma], b[na >> 1][na & 1], b[na >> 1][2 + (na & 1)]);
        }
        if (++s == 3) s = 0;
    }

    int lm = lane >> 2, ln = (lane & 3) * 2;
    int m_cta = blockIdx.y * 128;
    int n_cta = blockIdx.x * 128;

    float2 bias2[8];
    #pragma unroll
    for (int na = 0; na < 8; na++)
        bias2[na] = *(const float2*)(bias + n_cta + bn0 + na * 8 + ln);

    #pragma unroll
    for (int ma = 0; ma < 4; ma++) {
        #pragma unroll
        for (int half = 0; half < 2; half++) {
            int r = m_cta + am0 + ma * 16 + lm + half * 8;
            size_t drow = 0; const float* shortcut = nullptr;
            if (MODE == 2) {
                int wdx = r >> 6, n = r & 63;
                int b = wdx >> 10, wi = wdx & 1023;
                int hh = ((wi >> 5) << 3) + (n >> 3);
                int ww = ((wi & 31) << 3) + (n & 7);
                hh = (hh + 4) & 255; ww = (ww + 4) & 255;
                drow = ((size_t)b * 256 + hh) * 256 + ww;
                shortcut = aux2 + ((((size_t)b * 2) * 256 + hh) * 256 + ww) * 256;
            }
            #pragma unroll
            for (int na = 0; na < 8; na++) {
                int c = n_cta + bn0 + na * 8 + ln;
                float2 p = unp2(acc[ma][na][half]);
                float v0 = p.x + bias2[na].x;
                float v1 = p.y + bias2[na].y;
                if (MODE == 0) {
                    v0 *= 0.17677669529663687f; v1 *= 0.17677669529663687f;
                    *(uint32_t*)((__half*)Cout + (size_t)r * 256 + c) = packh(v0, v1);
                } else if (MODE == 1) {
                    *(uint32_t*)((__half*)Cout + (size_t)r * 512 + c) = packh(v0, v1);
                } else if (MODE == 2) {
                    float2 av = *(const float2*)(aux1 + (size_t)r * 256 + c);
                    float2 sv = *(const float2*)(shortcut + c);
                    *(float2*)((float*)Cout + drow * 256 + c) =
                        make_float2(v0 + av.x + sv.x, v1 + av.y + sv.y);
                } else if (MODE == 3) {
                    v0 = 0.5f * v0 * (1.0f + erff(v0 * 0.70710678118654752f));
                    v1 = 0.5f * v1 * (1.0f + erff(v1 * 0.70710678118654752f));
                    int mt = r >> 7, lr = r & 127;
                    int kt = c >> 6, lc = c & 63;
                    size_t tbase = ((size_t)(mt * 16 + kt)) << 14;
                    uint32_t off = SWZ((uint32_t)(lr * 128 + lc * 2));
                    *(uint32_t*)((unsigned char*)Cout + tbase + off) = packh(v0, v1);
                } else { // MODE 4
                    float2 av = *(const float2*)(aux1 + (size_t)r * 256 + c);
                    *(float2*)((float*)Cout + (size_t)r * 256 + c) =
                        make_float2(v0 + av.x, v1 + av.y);
                }
            }
        }
    }
}

// ---------------------------------------------------------------------------
// Tensor-core attention: 1 CTA (256 thr, 8 warps) per window, warp = head.
// fp16 operands, fp32 accumulate + fp32 softmax.
// ---------------------------------------------------------------------------
#define ATT_SMEM (96 * 1024)
__global__ __launch_bounds__(256) void attn_mma_kernel(
    const __half* __restrict__ q, const __half* __restrict__ kv,
    __half* __restrict__ att_bf,
    const float* __restrict__ mask, const float* __restrict__ biasf)
{
    extern __shared__ __align__(128) unsigned char dsm[];
    uint32_t sQ  = smem_u32(dsm);      // 64 rows x 32 chunks x 16B = 32KB
    uint32_t sKV = sQ + 32768;         // 64 rows x 64 chunks x 16B = 64KB

    int w = blockIdx.x;
    int tid = threadIdx.x, h = tid >> 5, lane = tid & 31;

    const unsigned char* qg  = (const unsigned char*)(q  + (size_t)w * 64 * 256);
    const unsigned char* kvg = (const unsigned char*)(kv + (size_t)w * 64 * 512);
    #pragma unroll
    for (int i = 0; i < 8; i++) {
        int g = tid + i * 256;
        int r = g >> 5, c = g & 31;
        cp16(sQ + (r * 32 + (c ^ (r & 7))) * 16, qg + (size_t)r * 512 + c * 16);
    }
    #pragma unroll
    for (int i = 0; i < 16; i++) {
        int g = tid + i * 256;
        int r = g >> 6, c = g & 63;
        cp16(sKV + (r * 64 + (c ^ (r & 7))) * 16, kvg + (size_t)r * 1024 + c * 16);
    }
    cp_commit(); cp_wait<0>();
    __syncthreads();

    int rsel = (lane & 7) + ((lane & 8) ? 8 : 0);
    int csel = (lane >> 4) & 1;

    uint32_t vb[4][4][2];
    #pragma unroll
    for (int kt = 0; kt < 4; kt++) {
        #pragma unroll
        for (int half = 0; half < 2; half++) {
            int vr = kt * 16 + rsel;
            int ch = 32 + h * 4 + half * 2 + csel;
            uint32_t r0, r1, r2, r3;
            ldm_x4t(r0, r1, r2, r3, sKV + (vr * 64 + (ch ^ (vr & 7))) * 16);
            vb[kt][half * 2 + 0][0] = r0; vb[kt][half * 2 + 0][1] = r1;
            vb[kt][half * 2 + 1][0] = r2; vb[kt][half * 2 + 1][1] = r3;
        }
    }

    const float* mbase = mask + (size_t)(w & 1023) * 4096;
    const float* bh = biasf + h * 4096;
    int ln2 = (lane & 3) * 2;

    #pragma unroll
    for (int mt = 0; mt < 4; mt++) {
        uint32_t qf[2][4];
        int qr = mt * 16 + rsel;
        #pragma unroll
        for (int t = 0; t < 2; t++) {
            int ch = h * 4 + t * 2 + csel;
            ldm_x4(qf[t][0], qf[t][1], qf[t][2], qf[t][3],
                   sQ + (qr * 32 + (ch ^ (qr & 7))) * 16);
        }
        float S[8][4];
        #pragma unroll
        for (int nt = 0; nt < 8; nt++)
            #pragma unroll
            for (int i = 0; i < 4; i++) S[nt][i] = 0.f;
        #pragma unroll
        for (int nt = 0; nt < 4; nt++) {
            uint32_t kb[2][4];
            int kr = nt * 16 + rsel;
            #pragma unroll
            for (int t = 0; t < 2; t++) {
                int ch = h * 4 + t * 2 + csel;
                ldm_x4(kb[t][0], kb[t][1], kb[t][2], kb[t][3],
                       sKV + (kr * 64 + (ch ^ (kr & 7))) * 16);
            }
            #pragma unroll
            for (int j = 0; j < 2; j++) {
                mma_hf32(S[2 * nt + j], qf[0], kb[0][j], kb[0][2 + j]);
                mma_hf32(S[2 * nt + j], qf[1], kb[1][j], kb[1][2 + j]);
            }
        }
        int r1 = mt * 16 + (lane >> 2), r2 = r1 + 8;
        #pragma unroll
        for (int nt = 0; nt < 8; nt++) {
            int cb = nt * 8 + ln2;
            float2 mk1 = *(const float2*)(mbase + r1 * 64 + cb);
            float2 mk2 = *(const float2*)(mbase + r2 * 64 + cb);
            float2 b1v = *(const float2*)(bh + r1 * 64 + cb);
            float2 b2v = *(const float2*)(bh + r2 * 64 + cb);
            S[nt][0] += mk1.x + b1v.x; S[nt][1] += mk1.y + b1v.y;
            S[nt][2] += mk2.x + b2v.x; S[nt][3] += mk2.y + b2v.y;
        }
        float mx1 = -1e30f, mx2 = -1e30f;
        #pragma unroll
        for (int nt = 0; nt < 8; nt++) {
            mx1 = fmaxf(mx1, fmaxf(S[nt][0], S[nt][1]));
            mx2 = fmaxf(mx2, fmaxf(S[nt][2], S[nt][3]));
        }
        mx1 = fmaxf(mx1, __shfl_xor_sync(0xffffffffu, mx1, 1));
        mx1 = fmaxf(mx1, __shfl_xor_sync(0xffffffffu, mx1, 2));
        mx2 = fmaxf(mx2, __shfl_xor_sync(0xffffffffu, mx2, 1));
        mx2 = fmaxf(mx2, __shfl_xor_sync(0xffffffffu, mx2, 2));
        float s1 = 0.f, s2 = 0.f;
        #pragma unroll
        for (int nt = 0; nt < 8; nt++) {
            S[nt][0] = __expf(S[nt][0] - mx1); s1 += S[nt][0];
            S[nt][1] = __expf(S[nt][1] - mx1); s1 += S[nt][1];
            S[nt][2] = __expf(S[nt][2] - mx2); s2 += S[nt][2];
            S[nt][3] = __expf(S[nt][3] - mx2); s2 += S[nt][3];
        }
        s1 += __shfl_xor_sync(0xffffffffu, s1, 1);
        s1 += __shfl_xor_sync(0xffffffffu, s1, 2);
        s2 += __shfl_xor_sync(0xffffffffu, s2, 1);
        s2 += __shfl_xor_sync(0xffffffffu, s2, 2);
        float i1 = 1.0f / s1, i2 = 1.0f / s2;
        uint32_t pa[4][4];
        #pragma unroll
        for (int kt = 0; kt < 4; kt++) {
            pa[kt][0] = packh(S[2*kt][0]   * i1, S[2*kt][1]   * i1);
            pa[kt][1] = packh(S[2*kt][2]   * i2, S[2*kt][3]   * i2);
            pa[kt][2] = packh(S[2*kt+1][0] * i1, S[2*kt+1][1] * i1);
            pa[kt][3] = packh(S[2*kt+1][2] * i2, S[2*kt+1][3] * i2);
        }
        float of[4][4];
        #pragma unroll
        for (int nd = 0; nd < 4; nd++)
            #pragma unroll
            for (int i = 0; i < 4; i++) of[nd][i] = 0.f;
        #pragma unroll
        for (int kt = 0; kt < 4; kt++)
            #pragma unroll
            for (int nd = 0; nd < 4; nd++)
                mma_hf32(of[nd], pa[kt], vb[kt][nd][0], vb[kt][nd][1]);
        int rg1 = (w << 6) + r1, rg2 = (w << 6) + r2;
        int mtg = rg1 >> 7;
        int lr1 = rg1 & 127, lr2 = rg2 & 127;
        #pragma unroll
        for (int nd = 0; nd < 4; nd++) {
            int c = h * 32 + nd * 8 + ln2;
            int ktg = c >> 6, lc = c & 63;
            size_t tbase = ((size_t)(mtg * 4 + ktg)) << 14;
            *(uint32_t*)((unsigned char*)att_bf + tbase + SWZ((uint32_t)(lr1 * 128 + lc * 2)))
                = packh(of[nd][0], of[nd][1]);
            *(uint32_t*)((unsigned char*)att_bf + tbase + SWZ((uint32_t)(lr2 * 128 + lc * 2)))
                = packh(of[nd][2], of[nd][3]);
        }
    }
}

// ---------------------------------------------------------------------------
extern "C" void kernel_launch(void* const* d_in, const int* in_sizes, int n_in,
                              void* d_out, int out_size)
{
    const float* x          = (const float*)d_in[0];
    const float* mask       = (const float*)d_in[1];
    const float* g1         = (const float*)d_in[2];
    const float* b1         = (const float*)d_in[3];
    const float* qw         = (const float*)d_in[4];
    const float* qb         = (const float*)d_in[5];
    const float* kvw        = (const float*)d_in[6];
    const float* kvb        = (const float*)d_in[7];
    const float* pw         = (const float*)d_in[8];
    const float* pb         = (const float*)d_in[9];
    const float* bias_table = (const float*)d_in[10];
    const float* g2         = (const float*)d_in[11];
    const float* b2         = (const float*)d_in[12];
    const float* w1         = (const float*)d_in[13];
    const float* bi1        = (const float*)d_in[14];
    const float* w2         = (const float*)d_in[15];
    const float* bi2        = (const float*)d_in[16];
    float* out = (float*)d_out;

    unsigned char* pool = nullptr;
    cudaGetSymbolAddress((void**)&pool, g_pool);

    float*   qin_f32 = (float*)(pool + OFF_QIN_F32);
    __half*  q_bf    = (__half*)(pool + OFF_Q_BF);
    __half*  kv_bf   = (__half*)(pool + OFF_KV_BF);
    __half*  qin_bf  = (__half*)(pool + OFF_QIN_BF);
    __half*  kvin_bf = (__half*)(pool + OFF_KVIN_BF);
    __half*  att_bf  = (__half*)(pool + OFF_ATT_BF);
    float*   x1      = (float*)(pool + OFF_X1_F32);
    __half*  wq_bf   = (__half*)(pool + OFF_WQ_BF);
    __half*  wkv_bf  = (__half*)(pool + OFF_WKV_BF);
    __half*  wp_bf   = (__half*)(pool + OFF_W_P_BF);
    __half*  w1_bf   = (__half*)(pool + OFF_W1_BF);
    __half*  w2_bf   = (__half*)(pool + OFF_W2_BF);
    float*   biasf   = (float*)(pool + OFF_BIASF);
    __half*  hid_bf  = (__half*)(pool + OFF_HID_BF);
    __half*  yn_bf   = (__half*)(pool + OFF_YN_BF);

    cudaFuncSetAttribute(gemm_mma<0>, cudaFuncAttributeMaxDynamicSharedMemorySize, GEMM_SMEM);
    cudaFuncSetAttribute(gemm_mma<1>, cudaFuncAttributeMaxDynamicSharedMemorySize, GEMM_SMEM);
    cudaFuncSetAttribute(gemm_mma<2>, cudaFuncAttributeMaxDynamicSharedMemorySize, GEMM_SMEM);
    cudaFuncSetAttribute(gemm_mma<3>, cudaFuncAttributeMaxDynamicSharedMemorySize, GEMM_SMEM);
    cudaFuncSetAttribute(gemm_mma<4>, cudaFuncAttributeMaxDynamicSharedMemorySize, GEMM_SMEM);
    cudaFuncSetAttribute(attn_mma_kernel, cudaFuncAttributeMaxDynamicSharedMemorySize, ATT_SMEM);

    // 0,1. merged weight conversion + bias expansion
    convall_kernel<<<384, 256>>>(qw, kvw, pw, w1, w2, wq_bf, wkv_bf, wp_bf, w1_bf, w2_bf);
    biasx_kernel<<<64, 64>>>(bias_table, biasf);

    // 2. LN1 + shift + window partition
    ln1_win_kernel<<<(2 * 2 * 256 * 256) / 8, 256>>>(x, g1, b1, qin_f32, qin_bf, kvin_bf);

    // 3. Q GEMM -> fp16 row-major (scaled by 1/sqrt(32))
    gemm_mma<0><<<dim3(2, 1024), 128, GEMM_SMEM>>>(qin_bf, wq_bf, qb, q_bf, 256, nullptr, nullptr);

    // 4. KV GEMM -> fp16 row-major
    gemm_mma<1><<<dim3(4, 1024), 128, GEMM_SMEM>>>(kvin_bf, wkv_bf, kvb, kv_bf, 256, nullptr, nullptr);

    // 5. tensor-core attention -> att fp16 tiles  (ncu capture lands here)
    attn_mma_kernel<<<2048, 256, ATT_SMEM>>>(q_bf, kv_bf, att_bf, mask, biasf);

    // 6. proj + residual(q_in fp32) + shortcut + inverse-roll scatter -> x1 fp32
    gemm_mma<2><<<dim3(2, 1024), 128, GEMM_SMEM>>>(att_bf, wp_bf, pb, x1, 256, qin_f32, x);

    // 7. LN2 -> yn fp16 tiles
    ln2_kernel<<<ROWS / 8, 256>>>(x1, g2, b2, yn_bf);

    // 8. MLP1 + gelu -> hid fp16 tiles
    gemm_mma<3><<<dim3(8, 1024), 128, GEMM_SMEM>>>(yn_bf, w1_bf, bi1, hid_bf, 256, nullptr, nullptr);

    // 9. MLP2 + residual(x1) -> out fp32
    gemm_mma<4><<<dim3(2, 1024), 128, GEMM_SMEM>>>(hid_bf, w2_bf, bi2, out, 1024, x1, nullptr);
}

// round 12
// speedup vs baseline: 1.0601x; 1.0358x over previous
#include <cuda_runtime.h>
#include <cuda_fp16.h>
#include <math.h>
#include <stdint.h>

// ---------------------------------------------------------------------------
#define ROWS 131072        // B*H*W tokens (= 2048 windows * 64)
#define HID  1024
#define MB   ((size_t)1024 * 1024)

#define POOL_BYTES ((size_t)836 * MB)
__device__ __align__(1024) unsigned char g_pool[POOL_BYTES];

#define OFF_Q_BF     ((size_t)128 * MB)
#define OFF_KV_BF    ((size_t)256 * MB)
#define OFF_QIN_BF   ((size_t)512 * MB)
#define OFF_KVIN_BF  ((size_t)576 * MB)
#define OFF_ATT_BF   ((size_t)640 * MB)
#define OFF_X1_H     ((size_t)704 * MB)      // fp16 row-major, 64MB
#define OFF_WQ_BF    ((size_t)832 * MB)
#define OFF_WKV_BF   (OFF_WQ_BF  + 256 * 256 * 2)
#define OFF_W_P_BF   (OFF_WKV_BF + 512 * 256 * 2)
#define OFF_W1_BF    (OFF_W_P_BF + 256 * 256 * 2)
#define OFF_W2_BF    (OFF_W1_BF  + 1024 * 256 * 2)
#define OFF_BIASF    (OFF_W2_BF  + 1024 * 256 * 2)   // [8][64][64] f32 = 128KB
#define OFF_HID_BF   ((size_t)0)
#define OFF_YN_BF    ((size_t)256 * MB)

// SW128 swizzle for 128B-row fp16 tiles
#define SWZ(o) ((o) ^ (((o) >> 3) & 0x70))

// ---------------------------------------------------------------------------
// PTX helpers (baseline sm_100-safe)
// ---------------------------------------------------------------------------
__device__ __forceinline__ uint32_t smem_u32(const void* p) {
    uint32_t a;
    asm("{ .reg .u64 t; cvta.to.shared.u64 t, %1; cvt.u32.u64 %0, t; }" : "=r"(a) : "l"(p));
    return a;
}
__device__ __forceinline__ void cp16(uint32_t s, const void* g) {
    asm volatile("cp.async.cg.shared.global [%0], [%1], 16;" :: "r"(s), "l"(g) : "memory");
}
__device__ __forceinline__ void cp_commit() { asm volatile("cp.async.commit_group;" ::: "memory"); }
template<int N> __device__ __forceinline__ void cp_wait() {
    asm volatile("cp.async.wait_group %0;" :: "n"(N) : "memory");
}
__device__ __forceinline__ void ldm_x4(uint32_t& r0, uint32_t& r1, uint32_t& r2, uint32_t& r3, uint32_t addr) {
    asm volatile("ldmatrix.sync.aligned.m8n8.x4.shared.b16 {%0,%1,%2,%3}, [%4];"
                 : "=r"(r0), "=r"(r1), "=r"(r2), "=r"(r3) : "r"(addr));
}
__device__ __forceinline__ void ldm_x4t(uint32_t& r0, uint32_t& r1, uint32_t& r2, uint32_t& r3, uint32_t addr) {
    asm volatile("ldmatrix.sync.aligned.m8n8.x4.trans.shared.b16 {%0,%1,%2,%3}, [%4];"
                 : "=r"(r0), "=r"(r1), "=r"(r2), "=r"(r3) : "r"(addr));
}
// fp16 inputs, fp16 accumulate
__device__ __forceinline__ void mma_h16(uint32_t* c, const uint32_t* a, uint32_t b0, uint32_t b1) {
    asm volatile(
        "mma.sync.aligned.m16n8k16.row.col.f16.f16.f16.f16 "
        "{%0,%1}, {%2,%3,%4,%5}, {%6,%7}, {%0,%1};"
        : "+r"(c[0]), "+r"(c[1])
        : "r"(a[0]), "r"(a[1]), "r"(a[2]), "r"(a[3]), "r"(b0), "r"(b1));
}
// fp16 inputs, fp32 accumulate (attention)
__device__ __forceinline__ void mma_hf32(float* c, const uint32_t* a, uint32_t b0, uint32_t b1) {
    asm volatile(
        "mma.sync.aligned.m16n8k16.row.col.f32.f16.f16.f32 "
        "{%0,%1,%2,%3}, {%4,%5,%6,%7}, {%8,%9}, {%0,%1,%2,%3};"
        : "+f"(c[0]), "+f"(c[1]), "+f"(c[2]), "+f"(c[3])
        : "r"(a[0]), "r"(a[1]), "r"(a[2]), "r"(a[3]), "r"(b0), "r"(b1));
}
__device__ __forceinline__ uint32_t packh(float a, float b) {
    __half2 p = __floats2half2_rn(a, b);
    return *(uint32_t*)&p;
}
__device__ __forceinline__ float2 unp2(uint32_t u) {
    return __half22float2(*(__half2*)&u);
}

// ---------------------------------------------------------------------------
// Merged weight conversion (fp32 -> fp16 tiles).
// ---------------------------------------------------------------------------
__global__ __launch_bounds__(256) void convall_kernel(
    const float* __restrict__ qw, const float* __restrict__ kvw,
    const float* __restrict__ pw, const float* __restrict__ w1,
    const float* __restrict__ w2,
    __half* __restrict__ dq, __half* __restrict__ dkv,
    __half* __restrict__ dp, __half* __restrict__ dw1,
    __half* __restrict__ dw2)
{
    int blk = blockIdx.x;
    const float* src; __half* dst; int K, base;
    if      (blk < 32)  { src = qw;  dst = dq;  K = 256;  base = 0;   }
    else if (blk < 96)  { src = kvw; dst = dkv; K = 256;  base = 32;  }
    else if (blk < 128) { src = pw;  dst = dp;  K = 256;  base = 96;  }
    else if (blk < 256) { src = w1;  dst = dw1; K = 256;  base = 128; }
    else                { src = w2;  dst = dw2; K = 1024; base = 256; }
    int gid = (blk - base) * 256 + threadIdx.x;
    int kdiv8 = K >> 3;
    int r  = gid / kdiv8;
    int c0 = (gid - r * kdiv8) << 3;
    const float4* s = (const float4*)(src + (size_t)r * K + c0);
    float4 f0 = s[0], f1 = s[1];
    uint4 v;
    v.x = packh(f0.x, f0.y); v.y = packh(f0.z, f0.w);
    v.z = packh(f1.x, f1.y); v.w = packh(f1.z, f1.w);
    int mt = r >> 7, kt = c0 >> 6, lr = r & 127, lc = c0 & 63;
    size_t tbase = ((size_t)(mt * (K >> 6) + kt)) << 14;
    uint32_t off = SWZ((uint32_t)(lr * 128 + lc * 2));
    *(uint4*)((unsigned char*)dst + tbase + off) = v;
}

// Expand rel-pos bias table -> biasf[8][64][64]
__global__ __launch_bounds__(64) void biasx_kernel(
    const float* __restrict__ btab, float* __restrict__ biasf)
{
    int n = blockIdx.x, m = threadIdx.x;
    int idx = (((n >> 3) - (m >> 3) + 7) * 15 + ((n & 7) - (m & 7) + 7)) * 8;
    #pragma unroll
    for (int h = 0; h < 8; h++)
        biasf[h * 4096 + n * 64 + m] = btab[idx + h];
}

// ---------------------------------------------------------------------------
// LN1 + roll(-4,-4) + window partition. Warp per token. fp16 tiles only.
// ---------------------------------------------------------------------------
__global__ __launch_bounds__(256) void ln1_win_kernel(
    const float* __restrict__ x, const float* __restrict__ gw, const float* __restrict__ bw,
    __half* __restrict__ qin_bf, __half* __restrict__ kvin_bf)
{
    int token = blockIdx.x * 8 + (threadIdx.x >> 5);
    int lane = threadIdx.x & 31;
    int w = token & 255, h = (token >> 8) & 255, d = (token >> 16) & 1, b = token >> 17;

    const float4* row = (const float4*)(x + (size_t)token * 256);
    float4 v0 = row[lane * 2], v1 = row[lane * 2 + 1];
    float s  = v0.x + v0.y + v0.z + v0.w + v1.x + v1.y + v1.z + v1.w;
    float ss = v0.x*v0.x + v0.y*v0.y + v0.z*v0.z + v0.w*v0.w
             + v1.x*v1.x + v1.y*v1.y + v1.z*v1.z + v1.w*v1.w;
    #pragma unroll
    for (int o = 16; o > 0; o >>= 1) {
        s  += __shfl_xor_sync(0xffffffffu, s,  o);
        ss += __shfl_xor_sync(0xffffffffu, ss, o);
    }
    float mean = s * (1.0f / 256.0f);
    float inv  = rsqrtf(ss * (1.0f / 256.0f) - mean * mean + 1e-5f);

    float4 ga = ((const float4*)gw)[lane * 2], gb = ((const float4*)gw)[lane * 2 + 1];
    float4 ba = ((const float4*)bw)[lane * 2], bb = ((const float4*)bw)[lane * 2 + 1];
    float4 o0, o1;
    o0.x = (v0.x - mean) * inv * ga.x + ba.x;
    o0.y = (v0.y - mean) * inv * ga.y + ba.y;
    o0.z = (v0.z - mean) * inv * ga.z + ba.z;
    o0.w = (v0.w - mean) * inv * ga.w + ba.w;
    o1.x = (v1.x - mean) * inv * gb.x + bb.x;
    o1.y = (v1.y - mean) * inv * gb.y + bb.y;
    o1.z = (v1.z - mean) * inv * gb.z + bb.z;
    o1.w = (v1.w - mean) * inv * gb.w + bb.w;

    int hs = (h - 4) & 255, ws = (w - 4) & 255;
    int wi = ((hs >> 3) << 5) | (ws >> 3);
    int n  = ((hs & 7) << 3) | (ws & 7);
    int drow = (((b << 10) | wi) << 6) | n;

    int c0 = lane * 8;
    uint4 bfv;
    bfv.x = packh(o0.x, o0.y); bfv.y = packh(o0.z, o0.w);
    bfv.z = packh(o1.x, o1.y); bfv.w = packh(o1.z, o1.w);

    int mt = drow >> 7, kt = c0 >> 6, lr = drow & 127, lc = c0 & 63;
    size_t tbase = ((size_t)(mt * 4 + kt)) << 14;
    uint32_t off = SWZ((uint32_t)(lr * 128 + lc * 2));
    __half* dst = (d == 0) ? qin_bf : kvin_bf;
    *(uint4*)((unsigned char*)dst + tbase + off) = bfv;
}

// ---------------------------------------------------------------------------
// LN2: x1 fp16 row-major -> yn fp16 tiles. Warp per token.
// ---------------------------------------------------------------------------
__global__ __launch_bounds__(256) void ln2_kernel(
    const __half* __restrict__ in, const float* __restrict__ gw, const float* __restrict__ bw,
    __half* __restrict__ out_bf)
{
    int token = blockIdx.x * 8 + (threadIdx.x >> 5);
    int lane = threadIdx.x & 31;
    uint4 hv = *(const uint4*)(in + (size_t)token * 256 + lane * 8);
    float2 f0 = unp2(hv.x), f1 = unp2(hv.y), f2 = unp2(hv.z), f3 = unp2(hv.w);
    float v[8] = { f0.x, f0.y, f1.x, f1.y, f2.x, f2.y, f3.x, f3.y };
    float s = 0.f, ss = 0.f;
    #pragma unroll
    for (int i = 0; i < 8; i++) { s += v[i]; ss += v[i] * v[i]; }
    #pragma unroll
    for (int o = 16; o > 0; o >>= 1) {
        s  += __shfl_xor_sync(0xffffffffu, s,  o);
        ss += __shfl_xor_sync(0xffffffffu, ss, o);
    }
    float mean = s * (1.0f / 256.0f);
    float inv  = rsqrtf(ss * (1.0f / 256.0f) - mean * mean + 1e-5f);

    float4 ga = ((const float4*)gw)[lane * 2], gb = ((const float4*)gw)[lane * 2 + 1];
    float4 ba = ((const float4*)bw)[lane * 2], bb = ((const float4*)bw)[lane * 2 + 1];
    float g[8] = { ga.x, ga.y, ga.z, ga.w, gb.x, gb.y, gb.z, gb.w };
    float bt[8] = { ba.x, ba.y, ba.z, ba.w, bb.x, bb.y, bb.z, bb.w };
    float o[8];
    #pragma unroll
    for (int i = 0; i < 8; i++) o[i] = (v[i] - mean) * inv * g[i] + bt[i];

    int c0 = lane * 8;
    uint4 bfv;
    bfv.x = packh(o[0], o[1]); bfv.y = packh(o[2], o[3]);
    bfv.z = packh(o[4], o[5]); bfv.w = packh(o[6], o[7]);
    int mt = token >> 7, kt = c0 >> 6, lr = token & 127, lc = c0 & 63;
    size_t tbase = ((size_t)(mt * 4 + kt)) << 14;
    uint32_t off = SWZ((uint32_t)(lr * 128 + lc * 2));
    *(uint4*)((unsigned char*)out_bf + tbase + off) = bfv;
}

// ---------------------------------------------------------------------------
// HMMA fp16 GEMM (fp16 accumulate): CTA 128x128, 4 warps (2Mx2N), warp 64x64.
// MODE 0: q_h    = fp16((acc+bias)/sqrt32)   row-major ld256
// MODE 1: kv_h   = fp16(acc+bias)            row-major ld512
// MODE 2: x1_h[scatter] = fp16(acc+bias + qin_tile[r,c] + x[b,0,hh,ww,c])
// MODE 3: hid tiles = fp16(gelu(acc+bias))
// MODE 4: out_f32 = acc+bias + x1_h[r,c]
// ---------------------------------------------------------------------------
#define GEMM_SMEM (98304)
template<int MODE>
__global__ __launch_bounds__(128, 2) void gemm_mma(
    const __half* __restrict__ A, const __half* __restrict__ B,
    const float* __restrict__ bias, void* __restrict__ Cout, int K,
    const void* __restrict__ aux1, const float* __restrict__ aux2)
{
    extern __shared__ __align__(1024) unsigned char dsm[];
    uint32_t sbase = smem_u32(dsm);
    uint32_t stA[3] = { sbase, sbase + 32768, sbase + 65536 };
    uint32_t stB[3] = { sbase + 16384, sbase + 49152, sbase + 81920 };

    int tid = threadIdx.x, wid = tid >> 5, lane = tid & 31;
    int KC = K >> 6;
    const unsigned char* Ab = (const unsigned char*)A + (((size_t)blockIdx.y * KC) << 14);
    const unsigned char* Bb = (const unsigned char*)B + (((size_t)blockIdx.x * KC) << 14);

    auto load_chunk = [&](int kc, int st) {
        const unsigned char* ga = Ab + ((size_t)kc << 14);
        const unsigned char* gb = Bb + ((size_t)kc << 14);
        #pragma unroll
        for (int i = 0; i < 8; i++) {
            int o = tid * 16 + i * 2048;
            cp16(stA[st] + o, ga + o);
            cp16(stB[st] + o, gb + o);
        }
        cp_commit();
    };

    int wm = wid & 1, wn = wid >> 1;
    int am0 = wm * 64, bn0 = wn * 64;
    int row_off = ((lane >> 3) & 1) * 8 + (lane & 7);
    int colbit  = ((lane >> 4) & 1) * 16;
    uint32_t xr = (uint32_t)((lane & 7) << 4);
    uint32_t aro[4], bro[4];
    #pragma unroll
    for (int ma = 0; ma < 4; ma++) aro[ma] = (uint32_t)((am0 + ma * 16 + row_off) * 128);
    #pragma unroll
    for (int nb = 0; nb < 4; nb++) bro[nb] = (uint32_t)((bn0 + nb * 16 + row_off) * 128);

    uint32_t acc[4][8][2];
    #pragma unroll
    for (int ma = 0; ma < 4; ma++)
        #pragma unroll
        for (int na = 0; na < 8; na++) { acc[ma][na][0] = 0u; acc[ma][na][1] = 0u; }

    load_chunk(0, 0);
    load_chunk(1, 1);
    int s = 0, ls = 2;
    for (int kc = 0; kc < KC; kc++) {
        if (kc == KC - 1) cp_wait<0>(); else cp_wait<1>();
        __syncthreads();
        if (kc + 2 < KC) {
            load_chunk(kc + 2, ls);
            if (++ls == 3) ls = 0;
        }
        #pragma unroll
        for (int ks = 0; ks < 4; ks++) {
            uint32_t cbyte = (uint32_t)(ks * 32 + colbit) ^ xr;
            uint32_t a[4][4], b[4][4];
            #pragma unroll
            for (int ma = 0; ma < 4; ma++)
                ldm_x4(a[ma][0], a[ma][1], a[ma][2], a[ma][3], stA[s] + aro[ma] + cbyte);
            #pragma unroll
            for (int nb = 0; nb < 4; nb++)
                ldm_x4(b[nb][0], b[nb][1], b[nb][2], b[nb][3], stB[s] + bro[nb] + cbyte);
            #pragma unroll
            for (int ma = 0; ma < 4; ma++)
                #pragma unroll
                for (int na = 0; na < 8; na++)
                    mma_h16(acc[ma][na], a[ma], b[na >> 1][na & 1], b[na >> 1][2 + (na & 1)]);
        }
        if (++s == 3) s = 0;
    }

    int lm = lane >> 2, ln = (lane & 3) * 2;
    int m_cta = blockIdx.y * 128;
    int n_cta = blockIdx.x * 128;

    float2 bias2[8];
    #pragma unroll
    for (int na = 0; na < 8; na++)
        bias2[na] = *(const float2*)(bias + n_cta + bn0 + na * 8 + ln);

    #pragma unroll
    for (int ma = 0; ma < 4; ma++) {
        #pragma unroll
        for (int half = 0; half < 2; half++) {
            int r = m_cta + am0 + ma * 16 + lm + half * 8;
            size_t drow = 0; const float* shortcut = nullptr;
            if (MODE == 2) {
                int wdx = r >> 6, n = r & 63;
                int b = wdx >> 10, wi = wdx & 1023;
                int hh = ((wi >> 5) << 3) + (n >> 3);
                int ww = ((wi & 31) << 3) + (n & 7);
                hh = (hh + 4) & 255; ww = (ww + 4) & 255;
                drow = ((size_t)b * 256 + hh) * 256 + ww;
                shortcut = aux2 + ((((size_t)b * 2) * 256 + hh) * 256 + ww) * 256;
            }
            #pragma unroll
            for (int na = 0; na < 8; na++) {
                int c = n_cta + bn0 + na * 8 + ln;
                float2 p = unp2(acc[ma][na][half]);
                float v0 = p.x + bias2[na].x;
                float v1 = p.y + bias2[na].y;
                if (MODE == 0) {
                    v0 *= 0.17677669529663687f; v1 *= 0.17677669529663687f;
                    *(uint32_t*)((__half*)Cout + (size_t)r * 256 + c) = packh(v0, v1);
                } else if (MODE == 1) {
                    *(uint32_t*)((__half*)Cout + (size_t)r * 512 + c) = packh(v0, v1);
                } else if (MODE == 2) {
                    // qin residual from fp16 tiles
                    int mtq = r >> 7, lrq = r & 127;
                    int ktq = c >> 6, lcq = c & 63;
                    size_t tb = ((size_t)(mtq * 4 + ktq)) << 14;
                    uint32_t qo = SWZ((uint32_t)(lrq * 128 + lcq * 2));
                    float2 av = unp2(*(const uint32_t*)((const unsigned char*)aux1 + tb + qo));
                    float2 sv = *(const float2*)(shortcut + c);
                    *(uint32_t*)((__half*)Cout + drow * 256 + c) =
                        packh(v0 + av.x + sv.x, v1 + av.y + sv.y);
                } else if (MODE == 3) {
                    v0 = 0.5f * v0 * (1.0f + erff(v0 * 0.70710678118654752f));
                    v1 = 0.5f * v1 * (1.0f + erff(v1 * 0.70710678118654752f));
                    int mt = r >> 7, lr = r & 127;
                    int kt = c >> 6, lc = c & 63;
                    size_t tbase = ((size_t)(mt * 16 + kt)) << 14;
                    uint32_t off = SWZ((uint32_t)(lr * 128 + lc * 2));
                    *(uint32_t*)((unsigned char*)Cout + tbase + off) = packh(v0, v1);
                } else { // MODE 4
                    float2 av = unp2(*(const uint32_t*)((const __half*)aux1 + (size_t)r * 256 + c));
                    *(float2*)((float*)Cout + (size_t)r * 256 + c) =
                        make_float2(v0 + av.x, v1 + av.y);
                }
            }
        }
    }
}

// ---------------------------------------------------------------------------
// Tensor-core attention: 1 CTA (256 thr, 8 warps) per window, warp = head.
// ---------------------------------------------------------------------------
#define ATT_SMEM (96 * 1024)
__global__ __launch_bounds__(256) void attn_mma_kernel(
    const __half* __restrict__ q, const __half* __restrict__ kv,
    __half* __restrict__ att_bf,
    const float* __restrict__ mask, const float* __restrict__ biasf)
{
    extern __shared__ __align__(128) unsigned char dsm[];
    uint32_t sQ  = smem_u32(dsm);
    uint32_t sKV = sQ + 32768;

    int w = blockIdx.x;
    int tid = threadIdx.x, h = tid >> 5, lane = tid & 31;

    const unsigned char* qg  = (const unsigned char*)(q  + (size_t)w * 64 * 256);
    const unsigned char* kvg = (const unsigned char*)(kv + (size_t)w * 64 * 512);
    #pragma unroll
    for (int i = 0; i < 8; i++) {
        int g = tid + i * 256;
        int r = g >> 5, c = g & 31;
        cp16(sQ + (r * 32 + (c ^ (r & 7))) * 16, qg + (size_t)r * 512 + c * 16);
    }
    #pragma unroll
    for (int i = 0; i < 16; i++) {
        int g = tid + i * 256;
        int r = g >> 6, c = g & 63;
        cp16(sKV + (r * 64 + (c ^ (r & 7))) * 16, kvg + (size_t)r * 1024 + c * 16);
    }
    cp_commit(); cp_wait<0>();
    __syncthreads();

    int rsel = (lane & 7) + ((lane & 8) ? 8 : 0);
    int csel = (lane >> 4) & 1;

    uint32_t vb[4][4][2];
    #pragma unroll
    for (int kt = 0; kt < 4; kt++) {
        #pragma unroll
        for (int half = 0; half < 2; half++) {
            int vr = kt * 16 + rsel;
            int ch = 32 + h * 4 + half * 2 + csel;
            uint32_t r0, r1, r2, r3;
            ldm_x4t(r0, r1, r2, r3, sKV + (vr * 64 + (ch ^ (vr & 7))) * 16);
            vb[kt][half * 2 + 0][0] = r0; vb[kt][half * 2 + 0][1] = r1;
            vb[kt][half * 2 + 1][0] = r2; vb[kt][half * 2 + 1][1] = r3;
        }
    }

    const float* mbase = mask + (size_t)(w & 1023) * 4096;
    const float* bh = biasf + h * 4096;
    int ln2v = (lane & 3) * 2;

    #pragma unroll
    for (int mt = 0; mt < 4; mt++) {
        uint32_t qf[2][4];
        int qr = mt * 16 + rsel;
        #pragma unroll
        for (int t = 0; t < 2; t++) {
            int ch = h * 4 + t * 2 + csel;
            ldm_x4(qf[t][0], qf[t][1], qf[t][2], qf[t][3],
                   sQ + (qr * 32 + (ch ^ (qr & 7))) * 16);
        }
        float S[8][4];
        #pragma unroll
        for (int nt = 0; nt < 8; nt++)
            #pragma unroll
            for (int i = 0; i < 4; i++) S[nt][i] = 0.f;
        #pragma unroll
        for (int nt = 0; nt < 4; nt++) {
            uint32_t kb[2][4];
            int kr = nt * 16 + rsel;
            #pragma unroll
            for (int t = 0; t < 2; t++) {
                int ch = h * 4 + t * 2 + csel;
                ldm_x4(kb[t][0], kb[t][1], kb[t][2], kb[t][3],
                       sKV + (kr * 64 + (ch ^ (kr & 7))) * 16);
            }
            #pragma unroll
            for (int j = 0; j < 2; j++) {
                mma_hf32(S[2 * nt + j], qf[0], kb[0][j], kb[0][2 + j]);
                mma_hf32(S[2 * nt + j], qf[1], kb[1][j], kb[1][2 + j]);
            }
        }
        int r1 = mt * 16 + (lane >> 2), r2 = r1 + 8;
        #pragma unroll
        for (int nt = 0; nt < 8; nt++) {
            int cb = nt * 8 + ln2v;
            float2 mk1 = *(const float2*)(mbase + r1 * 64 + cb);
            float2 mk2 = *(const float2*)(mbase + r2 * 64 + cb);
            float2 b1v = *(const float2*)(bh + r1 * 64 + cb);
            float2 b2v = *(const float2*)(bh + r2 * 64 + cb);
            S[nt][0] += mk1.x + b1v.x; S[nt][1] += mk1.y + b1v.y;
            S[nt][2] += mk2.x + b2v.x; S[nt][3] += mk2.y + b2v.y;
        }
        float mx1 = -1e30f, mx2 = -1e30f;
        #pragma unroll
        for (int nt = 0; nt < 8; nt++) {
            mx1 = fmaxf(mx1, fmaxf(S[nt][0], S[nt][1]));
            mx2 = fmaxf(mx2, fmaxf(S[nt][2], S[nt][3]));
        }
        mx1 = fmaxf(mx1, __shfl_xor_sync(0xffffffffu, mx1, 1));
        mx1 = fmaxf(mx1, __shfl_xor_sync(0xffffffffu, mx1, 2));
        mx2 = fmaxf(mx2, __shfl_xor_sync(0xffffffffu, mx2, 1));
        mx2 = fmaxf(mx2, __shfl_xor_sync(0xffffffffu, mx2, 2));
        float s1 = 0.f, s2 = 0.f;
        #pragma unroll
        for (int nt = 0; nt < 8; nt++) {
            S[nt][0] = __expf(S[nt][0] - mx1); s1 += S[nt][0];
            S[nt][1] = __expf(S[nt][1] - mx1); s1 += S[nt][1];
            S[nt][2] = __expf(S[nt][2] - mx2); s2 += S[nt][2];
            S[nt][3] = __expf(S[nt][3] - mx2); s2 += S[nt][3];
        }
        s1 += __shfl_xor_sync(0xffffffffu, s1, 1);
        s1 += __shfl_xor_sync(0xffffffffu, s1, 2);
        s2 += __shfl_xor_sync(0xffffffffu, s2, 1);
        s2 += __shfl_xor_sync(0xffffffffu, s2, 2);
        float i1 = 1.0f / s1, i2 = 1.0f / s2;
        uint32_t pa[4][4];
        #pragma unroll
        for (int kt = 0; kt < 4; kt++) {
            pa[kt][0] = packh(S[2*kt][0]   * i1, S[2*kt][1]   * i1);
            pa[kt][1] = packh(S[2*kt][2]   * i2, S[2*kt][3]   * i2);
            pa[kt][2] = packh(S[2*kt+1][0] * i1, S[2*kt+1][1] * i1);
            pa[kt][3] = packh(S[2*kt+1][2] * i2, S[2*kt+1][3] * i2);
        }
        float of[4][4];
        #pragma unroll
        for (int nd = 0; nd < 4; nd++)
            #pragma unroll
            for (int i = 0; i < 4; i++) of[nd][i] = 0.f;
        #pragma unroll
        for (int kt = 0; kt < 4; kt++)
            #pragma unroll
            for (int nd = 0; nd < 4; nd++)
                mma_hf32(of[nd], pa[kt], vb[kt][nd][0], vb[kt][nd][1]);
        int rg1 = (w << 6) + r1, rg2 = (w << 6) + r2;
        int mtg = rg1 >> 7;
        int lr1 = rg1 & 127, lr2 = rg2 & 127;
        #pragma unroll
        for (int nd = 0; nd < 4; nd++) {
            int c = h * 32 + nd * 8 + ln2v;
            int ktg = c >> 6, lc = c & 63;
            size_t tbase = ((size_t)(mtg * 4 + ktg)) << 14;
            *(uint32_t*)((unsigned char*)att_bf + tbase + SWZ((uint32_t)(lr1 * 128 + lc * 2)))
                = packh(of[nd][0], of[nd][1]);
            *(uint32_t*)((unsigned char*)att_bf + tbase + SWZ((uint32_t)(lr2 * 128 + lc * 2)))
                = packh(of[nd][2], of[nd][3]);
        }
    }
}

// ---------------------------------------------------------------------------
extern "C" void kernel_launch(void* const* d_in, const int* in_sizes, int n_in,
                              void* d_out, int out_size)
{
    const float* x          = (const float*)d_in[0];
    const float* mask       = (const float*)d_in[1];
    const float* g1         = (const float*)d_in[2];
    const float* b1         = (const float*)d_in[3];
    const float* qw         = (const float*)d_in[4];
    const float* qb         = (const float*)d_in[5];
    const float* kvw        = (const float*)d_in[6];
    const float* kvb        = (const float*)d_in[7];
    const float* pw         = (const float*)d_in[8];
    const float* pb         = (const float*)d_in[9];
    const float* bias_table = (const float*)d_in[10];
    const float* g2         = (const float*)d_in[11];
    const float* b2         = (const float*)d_in[12];
    const float* w1         = (const float*)d_in[13];
    const float* bi1        = (const float*)d_in[14];
    const float* w2         = (const float*)d_in[15];
    const float* bi2        = (const float*)d_in[16];
    float* out = (float*)d_out;

    unsigned char* pool = nullptr;
    cudaGetSymbolAddress((void**)&pool, g_pool);

    __half*  q_bf    = (__half*)(pool + OFF_Q_BF);
    __half*  kv_bf   = (__half*)(pool + OFF_KV_BF);
    __half*  qin_bf  = (__half*)(pool + OFF_QIN_BF);
    __half*  kvin_bf = (__half*)(pool + OFF_KVIN_BF);
    __half*  att_bf  = (__half*)(pool + OFF_ATT_BF);
    __half*  x1h     = (__half*)(pool + OFF_X1_H);
    __half*  wq_bf   = (__half*)(pool + OFF_WQ_BF);
    __half*  wkv_bf  = (__half*)(pool + OFF_WKV_BF);
    __half*  wp_bf   = (__half*)(pool + OFF_W_P_BF);
    __half*  w1_bf   = (__half*)(pool + OFF_W1_BF);
    __half*  w2_bf   = (__half*)(pool + OFF_W2_BF);
    float*   biasf   = (float*)(pool + OFF_BIASF);
    __half*  hid_bf  = (__half*)(pool + OFF_HID_BF);
    __half*  yn_bf   = (__half*)(pool + OFF_YN_BF);

    cudaFuncSetAttribute(gemm_mma<0>, cudaFuncAttributeMaxDynamicSharedMemorySize, GEMM_SMEM);
    cudaFuncSetAttribute(gemm_mma<1>, cudaFuncAttributeMaxDynamicSharedMemorySize, GEMM_SMEM);
    cudaFuncSetAttribute(gemm_mma<2>, cudaFuncAttributeMaxDynamicSharedMemorySize, GEMM_SMEM);
    cudaFuncSetAttribute(gemm_mma<3>, cudaFuncAttributeMaxDynamicSharedMemorySize, GEMM_SMEM);
    cudaFuncSetAttribute(gemm_mma<4>, cudaFuncAttributeMaxDynamicSharedMemorySize, GEMM_SMEM);
    cudaFuncSetAttribute(attn_mma_kernel, cudaFuncAttributeMaxDynamicSharedMemorySize, ATT_SMEM);

    // 0,1. merged weight conversion + bias expansion
    convall_kernel<<<384, 256>>>(qw, kvw, pw, w1, w2, wq_bf, wkv_bf, wp_bf, w1_bf, w2_bf);
    biasx_kernel<<<64, 64>>>(bias_table, biasf);

    // 2. LN1 + shift + window partition (fp16 tiles only)
    ln1_win_kernel<<<(2 * 2 * 256 * 256) / 8, 256>>>(x, g1, b1, qin_bf, kvin_bf);

    // 3. Q GEMM -> fp16 row-major (scaled by 1/sqrt(32))
    gemm_mma<0><<<dim3(2, 1024), 128, GEMM_SMEM>>>(qin_bf, wq_bf, qb, q_bf, 256, nullptr, nullptr);

    // 4. KV GEMM -> fp16 row-major
    gemm_mma<1><<<dim3(4, 1024), 128, GEMM_SMEM>>>(kvin_bf, wkv_bf, kvb, kv_bf, 256, nullptr, nullptr);

    // 5. tensor-core attention -> att fp16 tiles
    attn_mma_kernel<<<2048, 256, ATT_SMEM>>>(q_bf, kv_bf, att_bf, mask, biasf);

    // 6. proj + residual(qin fp16 tiles) + shortcut(x) + inverse-roll scatter -> x1 fp16
    gemm_mma<2><<<dim3(2, 1024), 128, GEMM_SMEM>>>(att_bf, wp_bf, pb, x1h, 256, qin_bf, x);

    // 7. LN2 (fp16 in) -> yn fp16 tiles
    ln2_kernel<<<ROWS / 8, 256>>>(x1h, g2, b2, yn_bf);

    // 8. MLP1 + gelu -> hid fp16 tiles
    gemm_mma<3><<<dim3(8, 1024), 128, GEMM_SMEM>>>(yn_bf, w1_bf, bi1, hid_bf, 256, nullptr, nullptr);

    // 9. MLP2 + residual(x1 fp16) -> out fp32
    gemm_mma<4><<<dim3(2, 1024), 128, GEMM_SMEM>>>(hid_bf, w2_bf, bi2, out, 1024, x1h, nullptr);
}

// round 14
// speedup vs baseline: 1.1723x; 1.1058x over previous
#include <cuda_runtime.h>
#include <cuda_fp16.h>
#include <math.h>
#include <stdint.h>

// ---------------------------------------------------------------------------
#define ROWS 131072
#define HID  1024
#define MB   ((size_t)1024 * 1024)

#define POOL_BYTES ((size_t)836 * MB)
__device__ __align__(1024) unsigned char g_pool[POOL_BYTES];

#define OFF_Q_BF     ((size_t)128 * MB)
#define OFF_KV_BF    ((size_t)256 * MB)
#define OFF_QIN_BF   ((size_t)512 * MB)
#define OFF_KVIN_BF  ((size_t)576 * MB)
#define OFF_ATT_BF   ((size_t)640 * MB)
#define OFF_X1_H     ((size_t)704 * MB)
#define OFF_WQ_BF    ((size_t)832 * MB)
#define OFF_WKV_BF   (OFF_WQ_BF  + 256 * 256 * 2)
#define OFF_W_P_BF   (OFF_WKV_BF + 512 * 256 * 2)
#define OFF_W1_BF    (OFF_W_P_BF + 256 * 256 * 2)
#define OFF_W2_BF    (OFF_W1_BF  + 1024 * 256 * 2)
#define OFF_BIASF    (OFF_W2_BF  + 1024 * 256 * 2)
#define OFF_HID_BF   ((size_t)0)
#define OFF_YN_BF    ((size_t)256 * MB)

#define SWZ(o) ((o) ^ (((o) >> 3) & 0x70))

// ---------------------------------------------------------------------------
__device__ __forceinline__ uint32_t smem_u32(const void* p) {
    uint32_t a;
    asm("{ .reg .u64 t; cvta.to.shared.u64 t, %1; cvt.u32.u64 %0, t; }" : "=r"(a) : "l"(p));
    return a;
}
__device__ __forceinline__ void cp16(uint32_t s, const void* g) {
    asm volatile("cp.async.cg.shared.global [%0], [%1], 16;" :: "r"(s), "l"(g) : "memory");
}
__device__ __forceinline__ void cp_commit() { asm volatile("cp.async.commit_group;" ::: "memory"); }
template<int N> __device__ __forceinline__ void cp_wait() {
    asm volatile("cp.async.wait_group %0;" :: "n"(N) : "memory");
}
__device__ __forceinline__ void ldm_x4(uint32_t& r0, uint32_t& r1, uint32_t& r2, uint32_t& r3, uint32_t addr) {
    asm volatile("ldmatrix.sync.aligned.m8n8.x4.shared.b16 {%0,%1,%2,%3}, [%4];"
                 : "=r"(r0), "=r"(r1), "=r"(r2), "=r"(r3) : "r"(addr));
}
__device__ __forceinline__ void ldm_x4t(uint32_t& r0, uint32_t& r1, uint32_t& r2, uint32_t& r3, uint32_t addr) {
    asm volatile("ldmatrix.sync.aligned.m8n8.x4.trans.shared.b16 {%0,%1,%2,%3}, [%4];"
                 : "=r"(r0), "=r"(r1), "=r"(r2), "=r"(r3) : "r"(addr));
}
__device__ __forceinline__ void mma_h16(uint32_t* c, const uint32_t* a, uint32_t b0, uint32_t b1) {
    asm volatile(
        "mma.sync.aligned.m16n8k16.row.col.f16.f16.f16.f16 "
        "{%0,%1}, {%2,%3,%4,%5}, {%6,%7}, {%0,%1};"
        : "+r"(c[0]), "+r"(c[1])
        : "r"(a[0]), "r"(a[1]), "r"(a[2]), "r"(a[3]), "r"(b0), "r"(b1));
}
__device__ __forceinline__ void mma_hf32(float* c, const uint32_t* a, uint32_t b0, uint32_t b1) {
    asm volatile(
        "mma.sync.aligned.m16n8k16.row.col.f32.f16.f16.f32 "
        "{%0,%1,%2,%3}, {%4,%5,%6,%7}, {%8,%9}, {%0,%1,%2,%3};"
        : "+f"(c[0]), "+f"(c[1]), "+f"(c[2]), "+f"(c[3])
        : "r"(a[0]), "r"(a[1]), "r"(a[2]), "r"(a[3]), "r"(b0), "r"(b1));
}
__device__ __forceinline__ uint32_t packh(float a, float b) {
    __half2 p = __floats2half2_rn(a, b);
    return *(uint32_t*)&p;
}
__device__ __forceinline__ float2 unp2(uint32_t u) {
    return __half22float2(*(__half2*)&u);
}

// ---------------------------------------------------------------------------
// Weight conversion + bias expansion, one launch.
// blocks [0,384): weights; [384,400): biasf expansion (4 rows per block)
// ---------------------------------------------------------------------------
__global__ __launch_bounds__(256) void convall_kernel(
    const float* __restrict__ qw, const float* __restrict__ kvw,
    const float* __restrict__ pw, const float* __restrict__ w1,
    const float* __restrict__ w2, const float* __restrict__ btab,
    __half* __restrict__ dq, __half* __restrict__ dkv,
    __half* __restrict__ dp, __half* __restrict__ dw1,
    __half* __restrict__ dw2, float* __restrict__ biasf)
{
    int blk = blockIdx.x;
    if (blk >= 384) {
        int n = (blk - 384) * 4 + (threadIdx.x >> 6);   // 0..63
        int m = threadIdx.x & 63;
        int idx = (((n >> 3) - (m >> 3) + 7) * 15 + ((n & 7) - (m & 7) + 7)) * 8;
        #pragma unroll
        for (int h = 0; h < 8; h++)
            biasf[h * 4096 + n * 64 + m] = btab[idx + h];
        return;
    }
    const float* src; __half* dst; int K, base;
    if      (blk < 32)  { src = qw;  dst = dq;  K = 256;  base = 0;   }
    else if (blk < 96)  { src = kvw; dst = dkv; K = 256;  base = 32;  }
    else if (blk < 128) { src = pw;  dst = dp;  K = 256;  base = 96;  }
    else if (blk < 256) { src = w1;  dst = dw1; K = 256;  base = 128; }
    else                { src = w2;  dst = dw2; K = 1024; base = 256; }
    int gid = (blk - base) * 256 + threadIdx.x;
    int kdiv8 = K >> 3;
    int r  = gid / kdiv8;
    int c0 = (gid - r * kdiv8) << 3;
    const float4* s = (const float4*)(src + (size_t)r * K + c0);
    float4 f0 = s[0], f1 = s[1];
    uint4 v;
    v.x = packh(f0.x, f0.y); v.y = packh(f0.z, f0.w);
    v.z = packh(f1.x, f1.y); v.w = packh(f1.z, f1.w);
    int mt = r >> 7, kt = c0 >> 6, lr = r & 127, lc = c0 & 63;
    size_t tbase = ((size_t)(mt * (K >> 6) + kt)) << 14;
    uint32_t off = SWZ((uint32_t)(lr * 128 + lc * 2));
    *(uint4*)((unsigned char*)dst + tbase + off) = v;
}

// ---------------------------------------------------------------------------
// LN1 + roll + window partition -> fp16 tiles. Warp per token.
// ---------------------------------------------------------------------------
__global__ __launch_bounds__(256) void ln1_win_kernel(
    const float* __restrict__ x, const float* __restrict__ gw, const float* __restrict__ bw,
    __half* __restrict__ qin_bf, __half* __restrict__ kvin_bf)
{
    int token = blockIdx.x * 8 + (threadIdx.x >> 5);
    int lane = threadIdx.x & 31;
    int w = token & 255, h = (token >> 8) & 255, d = (token >> 16) & 1, b = token >> 17;

    const float4* row = (const float4*)(x + (size_t)token * 256);
    float4 v0 = row[lane * 2], v1 = row[lane * 2 + 1];
    float s  = v0.x + v0.y + v0.z + v0.w + v1.x + v1.y + v1.z + v1.w;
    float ss = v0.x*v0.x + v0.y*v0.y + v0.z*v0.z + v0.w*v0.w
             + v1.x*v1.x + v1.y*v1.y + v1.z*v1.z + v1.w*v1.w;
    #pragma unroll
    for (int o = 16; o > 0; o >>= 1) {
        s  += __shfl_xor_sync(0xffffffffu, s,  o);
        ss += __shfl_xor_sync(0xffffffffu, ss, o);
    }
    float mean = s * (1.0f / 256.0f);
    float inv  = rsqrtf(ss * (1.0f / 256.0f) - mean * mean + 1e-5f);

    float4 ga = ((const float4*)gw)[lane * 2], gb = ((const float4*)gw)[lane * 2 + 1];
    float4 ba = ((const float4*)bw)[lane * 2], bb = ((const float4*)bw)[lane * 2 + 1];
    float4 o0, o1;
    o0.x = (v0.x - mean) * inv * ga.x + ba.x;
    o0.y = (v0.y - mean) * inv * ga.y + ba.y;
    o0.z = (v0.z - mean) * inv * ga.z + ba.z;
    o0.w = (v0.w - mean) * inv * ga.w + ba.w;
    o1.x = (v1.x - mean) * inv * gb.x + bb.x;
    o1.y = (v1.y - mean) * inv * gb.y + bb.y;
    o1.z = (v1.z - mean) * inv * gb.z + bb.z;
    o1.w = (v1.w - mean) * inv * gb.w + bb.w;

    int hs = (h - 4) & 255, ws = (w - 4) & 255;
    int wi = ((hs >> 3) << 5) | (ws >> 3);
    int n  = ((hs & 7) << 3) | (ws & 7);
    int drow = (((b << 10) | wi) << 6) | n;

    int c0 = lane * 8;
    uint4 bfv;
    bfv.x = packh(o0.x, o0.y); bfv.y = packh(o0.z, o0.w);
    bfv.z = packh(o1.x, o1.y); bfv.w = packh(o1.z, o1.w);

    int mt = drow >> 7, kt = c0 >> 6, lr = drow & 127, lc = c0 & 63;
    size_t tbase = ((size_t)(mt * 4 + kt)) << 14;
    uint32_t off = SWZ((uint32_t)(lr * 128 + lc * 2));
    __half* dst = (d == 0) ? qin_bf : kvin_bf;
    *(uint4*)((unsigned char*)dst + tbase + off) = bfv;
}

// ---------------------------------------------------------------------------
// LN2: x1 fp16 row-major -> yn fp16 tiles.
// ---------------------------------------------------------------------------
__global__ __launch_bounds__(256) void ln2_kernel(
    const __half* __restrict__ in, const float* __restrict__ gw, const float* __restrict__ bw,
    __half* __restrict__ out_bf)
{
    int token = blockIdx.x * 8 + (threadIdx.x >> 5);
    int lane = threadIdx.x & 31;
    uint4 hv = *(const uint4*)(in + (size_t)token * 256 + lane * 8);
    float2 f0 = unp2(hv.x), f1 = unp2(hv.y), f2 = unp2(hv.z), f3 = unp2(hv.w);
    float v[8] = { f0.x, f0.y, f1.x, f1.y, f2.x, f2.y, f3.x, f3.y };
    float s = 0.f, ss = 0.f;
    #pragma unroll
    for (int i = 0; i < 8; i++) { s += v[i]; ss += v[i] * v[i]; }
    #pragma unroll
    for (int o = 16; o > 0; o >>= 1) {
        s  += __shfl_xor_sync(0xffffffffu, s,  o);
        ss += __shfl_xor_sync(0xffffffffu, ss, o);
    }
    float mean = s * (1.0f / 256.0f);
    float inv  = rsqrtf(ss * (1.0f / 256.0f) - mean * mean + 1e-5f);

    float4 ga = ((const float4*)gw)[lane * 2], gb = ((const float4*)gw)[lane * 2 + 1];
    float4 ba = ((const float4*)bw)[lane * 2], bb = ((const float4*)bw)[lane * 2 + 1];
    float g[8] = { ga.x, ga.y, ga.z, ga.w, gb.x, gb.y, gb.z, gb.w };
    float bt[8] = { ba.x, ba.y, ba.z, ba.w, bb.x, bb.y, bb.z, bb.w };
    float o[8];
    #pragma unroll
    for (int i = 0; i < 8; i++) o[i] = (v[i] - mean) * inv * g[i] + bt[i];

    int c0 = lane * 8;
    uint4 bfv;
    bfv.x = packh(o[0], o[1]); bfv.y = packh(o[2], o[3]);
    bfv.z = packh(o[4], o[5]); bfv.w = packh(o[6], o[7]);
    int mt = token >> 7, kt = c0 >> 6, lr = token & 127, lc = c0 & 63;
    size_t tbase = ((size_t)(mt * 4 + kt)) << 14;
    uint32_t off = SWZ((uint32_t)(lr * 128 + lc * 2));
    *(uint4*)((unsigned char*)out_bf + tbase + off) = bfv;
}

// ---------------------------------------------------------------------------
// HMMA fp16 GEMM, 2-stage cp.async (64KB smem), 3 CTAs/SM.
// CTA 128x128, 4 warps (2Mx2N), warp 64x64, fp16 accumulate.
// MODE 2: x1_h[scatter] = fp16(acc+bias + qin_tile + x_shortcut)
// MODE 3: hid tiles = fp16(gelu(acc+bias))
// MODE 4: out_f32 = acc+bias + x1_h
// MODE 5: fused QKV: bx<2 -> Q (scale, ld256); bx>=2 -> KV (ld512)
// ---------------------------------------------------------------------------
#define GEMM_SMEM (65536)
template<int MODE>
__global__ __launch_bounds__(128, 3) void gemm_mma(
    const __half* __restrict__ A, const __half* __restrict__ B,
    const float* __restrict__ bias, void* __restrict__ Cout, int K,
    const void* __restrict__ aux1, const float* __restrict__ aux2,
    const __half* __restrict__ A2, const __half* __restrict__ B2,
    const float* __restrict__ bias2, void* __restrict__ C2)
{
    extern __shared__ __align__(1024) unsigned char dsm[];
    uint32_t sbase = smem_u32(dsm);
    uint32_t stA[2] = { sbase,         sbase + 32768 };
    uint32_t stB[2] = { sbase + 16384, sbase + 49152 };

    int tid = threadIdx.x, wid = tid >> 5, lane = tid & 31;
    int KC = K >> 6;

    bool isQ = true;
    int n_blk = blockIdx.x;
    const __half* Ause = A;
    const __half* Buse = B;
    const float* bias_use = bias;
    if (MODE == 5) {
        isQ = (blockIdx.x < 2);
        n_blk = isQ ? blockIdx.x : blockIdx.x - 2;
        Ause = isQ ? A : A2;
        Buse = isQ ? B : B2;
        bias_use = isQ ? bias : bias2;
    }

    const unsigned char* Ab = (const unsigned char*)Ause + (((size_t)blockIdx.y * KC) << 14);
    const unsigned char* Bb = (const unsigned char*)Buse + (((size_t)n_blk * KC) << 14);

    auto load_chunk = [&](int kc, int st) {
        const unsigned char* ga = Ab + ((size_t)kc << 14);
        const unsigned char* gb = Bb + ((size_t)kc << 14);
        #pragma unroll
        for (int i = 0; i < 8; i++) {
            int o = tid * 16 + i * 2048;
            cp16(stA[st] + o, ga + o);
            cp16(stB[st] + o, gb + o);
        }
        cp_commit();
    };

    int wm = wid & 1, wn = wid >> 1;
    int am0 = wm * 64, bn0 = wn * 64;
    int row_off = ((lane >> 3) & 1) * 8 + (lane & 7);
    int colbit  = ((lane >> 4) & 1) * 16;
    uint32_t xr = (uint32_t)((lane & 7) << 4);
    uint32_t aro[4], bro[4];
    #pragma unroll
    for (int ma = 0; ma < 4; ma++) aro[ma] = (uint32_t)((am0 + ma * 16 + row_off) * 128);
    #pragma unroll
    for (int nb = 0; nb < 4; nb++) bro[nb] = (uint32_t)((bn0 + nb * 16 + row_off) * 128);

    uint32_t acc[4][8][2];
    #pragma unroll
    for (int ma = 0; ma < 4; ma++)
        #pragma unroll
        for (int na = 0; na < 8; na++) { acc[ma][na][0] = 0u; acc[ma][na][1] = 0u; }

    load_chunk(0, 0);
    for (int kc = 0; kc < KC; kc++) {
        int s = kc & 1;
        if (kc + 1 < KC) { load_chunk(kc + 1, s ^ 1); cp_wait<1>(); }
        else             { cp_wait<0>(); }
        __syncthreads();
        #pragma unroll
        for (int ks = 0; ks < 4; ks++) {
            uint32_t cbyte = (uint32_t)(ks * 32 + colbit) ^ xr;
            uint32_t a[4][4], b[4][4];
            #pragma unroll
            for (int ma = 0; ma < 4; ma++)
                ldm_x4(a[ma][0], a[ma][1], a[ma][2], a[ma][3], stA[s] + aro[ma] + cbyte);
            #pragma unroll
            for (int nb = 0; nb < 4; nb++)
                ldm_x4(b[nb][0], b[nb][1], b[nb][2], b[nb][3], stB[s] + bro[nb] + cbyte);
            #pragma unroll
            for (int ma = 0; ma < 4; ma++)
                #pragma unroll
                for (int na = 0; na < 8; na++)
                    mma_h16(acc[ma][na], a[ma], b[na >> 1][na & 1], b[na >> 1][2 + (na & 1)]);
        }
        __syncthreads();
    }

    int lm = lane >> 2, ln = (lane & 3) * 2;
    int m_cta = blockIdx.y * 128;
    int n_cta = n_blk * 128;

    float2 bias2r[8];
    #pragma unroll
    for (int na = 0; na < 8; na++)
        bias2r[na] = *(const float2*)(bias_use + n_cta + bn0 + na * 8 + ln);

    #pragma unroll
    for (int ma = 0; ma < 4; ma++) {
        #pragma unroll
        for (int half = 0; half < 2; half++) {
            int r = m_cta + am0 + ma * 16 + lm + half * 8;
            size_t drow = 0; const float* shortcut = nullptr;
            if (MODE == 2) {
                int wdx = r >> 6, n = r & 63;
                int b = wdx >> 10, wi = wdx & 1023;
                int hh = ((wi >> 5) << 3) + (n >> 3);
                int ww = ((wi & 31) << 3) + (n & 7);
                hh = (hh + 4) & 255; ww = (ww + 4) & 255;
                drow = ((size_t)b * 256 + hh) * 256 + ww;
                shortcut = aux2 + ((((size_t)b * 2) * 256 + hh) * 256 + ww) * 256;
            }
            #pragma unroll
            for (int na = 0; na < 8; na++) {
                int c = n_cta + bn0 + na * 8 + ln;
                float2 p = unp2(acc[ma][na][half]);
                float v0 = p.x + bias2r[na].x;
                float v1 = p.y + bias2r[na].y;
                if (MODE == 5) {
                    if (isQ) {
                        v0 *= 0.17677669529663687f; v1 *= 0.17677669529663687f;
                        *(uint32_t*)((__half*)Cout + (size_t)r * 256 + c) = packh(v0, v1);
                    } else {
                        *(uint32_t*)((__half*)C2 + (size_t)r * 512 + c) = packh(v0, v1);
                    }
                } else if (MODE == 2) {
                    int mtq = r >> 7, lrq = r & 127;
                    int ktq = c >> 6, lcq = c & 63;
                    size_t tb = ((size_t)(mtq * 4 + ktq)) << 14;
                    uint32_t qo = SWZ((uint32_t)(lrq * 128 + lcq * 2));
                    float2 av = unp2(*(const uint32_t*)((const unsigned char*)aux1 + tb + qo));
                    float2 sv = *(const float2*)(shortcut + c);
                    *(uint32_t*)((__half*)Cout + drow * 256 + c) =
                        packh(v0 + av.x + sv.x, v1 + av.y + sv.y);
                } else if (MODE == 3) {
                    v0 = 0.5f * v0 * (1.0f + erff(v0 * 0.70710678118654752f));
                    v1 = 0.5f * v1 * (1.0f + erff(v1 * 0.70710678118654752f));
                    int mt = r >> 7, lr = r & 127;
                    int kt = c >> 6, lc = c & 63;
                    size_t tbase = ((size_t)(mt * 16 + kt)) << 14;
                    uint32_t off = SWZ((uint32_t)(lr * 128 + lc * 2));
                    *(uint32_t*)((unsigned char*)Cout + tbase + off) = packh(v0, v1);
                } else { // MODE 4
                    float2 av = unp2(*(const uint32_t*)((const __half*)aux1 + (size_t)r * 256 + c));
                    *(float2*)((float*)Cout + (size_t)r * 256 + c) =
                        make_float2(v0 + av.x, v1 + av.y);
                }
            }
        }
    }
}

// ---------------------------------------------------------------------------
// Tensor-core attention: 1 CTA (256 thr, 8 warps) per window, warp = head.
// ---------------------------------------------------------------------------
#define ATT_SMEM (96 * 1024)
__global__ __launch_bounds__(256) void attn_mma_kernel(
    const __half* __restrict__ q, const __half* __restrict__ kv,
    __half* __restrict__ att_bf,
    const float* __restrict__ mask, const float* __restrict__ biasf)
{
    extern __shared__ __align__(128) unsigned char dsm[];
    uint32_t sQ  = smem_u32(dsm);
    uint32_t sKV = sQ + 32768;

    int w = blockIdx.x;
    int tid = threadIdx.x, h = tid >> 5, lane = tid & 31;

    const unsigned char* qg  = (const unsigned char*)(q  + (size_t)w * 64 * 256);
    const unsigned char* kvg = (const unsigned char*)(kv + (size_t)w * 64 * 512);
    #pragma unroll
    for (int i = 0; i < 8; i++) {
        int g = tid + i * 256;
        int r = g >> 5, c = g & 31;
        cp16(sQ + (r * 32 + (c ^ (r & 7))) * 16, qg + (size_t)r * 512 + c * 16);
    }
    #pragma unroll
    for (int i = 0; i < 16; i++) {
        int g = tid + i * 256;
        int r = g >> 6, c = g & 63;
        cp16(sKV + (r * 64 + (c ^ (r & 7))) * 16, kvg + (size_t)r * 1024 + c * 16);
    }
    cp_commit(); cp_wait<0>();
    __syncthreads();

    int rsel = (lane & 7) + ((lane & 8) ? 8 : 0);
    int csel = (lane >> 4) & 1;

    uint32_t vb[4][4][2];
    #pragma unroll
    for (int kt = 0; kt < 4; kt++) {
        #pragma unroll
        for (int half = 0; half < 2; half++) {
            int vr = kt * 16 + rsel;
            int ch = 32 + h * 4 + half * 2 + csel;
            uint32_t r0, r1, r2, r3;
            ldm_x4t(r0, r1, r2, r3, sKV + (vr * 64 + (ch ^ (vr & 7))) * 16);
            vb[kt][half * 2 + 0][0] = r0; vb[kt][half * 2 + 0][1] = r1;
            vb[kt][half * 2 + 1][0] = r2; vb[kt][half * 2 + 1][1] = r3;
        }
    }

    const float* mbase = mask + (size_t)(w & 1023) * 4096;
    const float* bh = biasf + h * 4096;
    int ln2v = (lane & 3) * 2;

    #pragma unroll
    for (int mt = 0; mt < 4; mt++) {
        uint32_t qf[2][4];
        int qr = mt * 16 + rsel;
        #pragma unroll
        for (int t = 0; t < 2; t++) {
            int ch = h * 4 + t * 2 + csel;
            ldm_x4(qf[t][0], qf[t][1], qf[t][2], qf[t][3],
                   sQ + (qr * 32 + (ch ^ (qr & 7))) * 16);
        }
        float S[8][4];
        #pragma unroll
        for (int nt = 0; nt < 8; nt++)
            #pragma unroll
            for (int i = 0; i < 4; i++) S[nt][i] = 0.f;
        #pragma unroll
        for (int nt = 0; nt < 4; nt++) {
            uint32_t kb[2][4];
            int kr = nt * 16 + rsel;
            #pragma unroll
            for (int t = 0; t < 2; t++) {
                int ch = h * 4 + t * 2 + csel;
                ldm_x4(kb[t][0], kb[t][1], kb[t][2], kb[t][3],
                       sKV + (kr * 64 + (ch ^ (kr & 7))) * 16);
            }
            #pragma unroll
            for (int j = 0; j < 2; j++) {
                mma_hf32(S[2 * nt + j], qf[0], kb[0][j], kb[0][2 + j]);
                mma_hf32(S[2 * nt + j], qf[1], kb[1][j], kb[1][2 + j]);
            }
        }
        int r1 = mt * 16 + (lane >> 2), r2 = r1 + 8;
        #pragma unroll
        for (int nt = 0; nt < 8; nt++) {
            int cb = nt * 8 + ln2v;
            float2 mk1 = *(const float2*)(mbase + r1 * 64 + cb);
            float2 mk2 = *(const float2*)(mbase + r2 * 64 + cb);
            float2 b1v = *(const float2*)(bh + r1 * 64 + cb);
            float2 b2v = *(const float2*)(bh + r2 * 64 + cb);
            S[nt][0] += mk1.x + b1v.x; S[nt][1] += mk1.y + b1v.y;
            S[nt][2] += mk2.x + b2v.x; S[nt][3] += mk2.y + b2v.y;
        }
        float mx1 = -1e30f, mx2 = -1e30f;
        #pragma unroll
        for (int nt = 0; nt < 8; nt++) {
            mx1 = fmaxf(mx1, fmaxf(S[nt][0], S[nt][1]));
            mx2 = fmaxf(mx2, fmaxf(S[nt][2], S[nt][3]));
        }
        mx1 = fmaxf(mx1, __shfl_xor_sync(0xffffffffu, mx1, 1));
        mx1 = fmaxf(mx1, __shfl_xor_sync(0xffffffffu, mx1, 2));
        mx2 = fmaxf(mx2, __shfl_xor_sync(0xffffffffu, mx2, 1));
        mx2 = fmaxf(mx2, __shfl_xor_sync(0xffffffffu, mx2, 2));
        float s1 = 0.f, s2 = 0.f;
        #pragma unroll
        for (int nt = 0; nt < 8; nt++) {
            S[nt][0] = __expf(S[nt][0] - mx1); s1 += S[nt][0];
            S[nt][1] = __expf(S[nt][1] - mx1); s1 += S[nt][1];
            S[nt][2] = __expf(S[nt][2] - mx2); s2 += S[nt][2];
            S[nt][3] = __expf(S[nt][3] - mx2); s2 += S[nt][3];
        }
        s1 += __shfl_xor_sync(0xffffffffu, s1, 1);
        s1 += __shfl_xor_sync(0xffffffffu, s1, 2);
        s2 += __shfl_xor_sync(0xffffffffu, s2, 1);
        s2 += __shfl_xor_sync(0xffffffffu, s2, 2);
        float i1 = 1.0f / s1, i2 = 1.0f / s2;
        uint32_t pa[4][4];
        #pragma unroll
        for (int kt = 0; kt < 4; kt++) {
            pa[kt][0] = packh(S[2*kt][0]   * i1, S[2*kt][1]   * i1);
            pa[kt][1] = packh(S[2*kt][2]   * i2, S[2*kt][3]   * i2);
            pa[kt][2] = packh(S[2*kt+1][0] * i1, S[2*kt+1][1] * i1);
            pa[kt][3] = packh(S[2*kt+1][2] * i2, S[2*kt+1][3] * i2);
        }
        float of[4][4];
        #pragma unroll
        for (int nd = 0; nd < 4; nd++)
            #pragma unroll
            for (int i = 0; i < 4; i++) of[nd][i] = 0.f;
        #pragma unroll
        for (int kt = 0; kt < 4; kt++)
            #pragma unroll
            for (int nd = 0; nd < 4; nd++)
                mma_hf32(of[nd], pa[kt], vb[kt][nd][0], vb[kt][nd][1]);
        int rg1 = (w << 6) + r1, rg2 = (w << 6) + r2;
        int mtg = rg1 >> 7;
        int lr1 = rg1 & 127, lr2 = rg2 & 127;
        #pragma unroll
        for (int nd = 0; nd < 4; nd++) {
            int c = h * 32 + nd * 8 + ln2v;
            int ktg = c >> 6, lc = c & 63;
            size_t tbase = ((size_t)(mtg * 4 + ktg)) << 14;
            *(uint32_t*)((unsigned char*)att_bf + tbase + SWZ((uint32_t)(lr1 * 128 + lc * 2)))
                = packh(of[nd][0], of[nd][1]);
            *(uint32_t*)((unsigned char*)att_bf + tbase + SWZ((uint32_t)(lr2 * 128 + lc * 2)))
                = packh(of[nd][2], of[nd][3]);
        }
    }
}

// ---------------------------------------------------------------------------
extern "C" void kernel_launch(void* const* d_in, const int* in_sizes, int n_in,
                              void* d_out, int out_size)
{
    const float* x          = (const float*)d_in[0];
    const float* mask       = (const float*)d_in[1];
    const float* g1         = (const float*)d_in[2];
    const float* b1         = (const float*)d_in[3];
    const float* qw         = (const float*)d_in[4];
    const float* qb         = (const float*)d_in[5];
    const float* kvw        = (const float*)d_in[6];
    const float* kvb        = (const float*)d_in[7];
    const float* pw         = (const float*)d_in[8];
    const float* pb         = (const float*)d_in[9];
    const float* bias_table = (const float*)d_in[10];
    const float* g2         = (const float*)d_in[11];
    const float* b2         = (const float*)d_in[12];
    const float* w1         = (const float*)d_in[13];
    const float* bi1        = (const float*)d_in[14];
    const float* w2         = (const float*)d_in[15];
    const float* bi2        = (const float*)d_in[16];
    float* out = (float*)d_out;

    unsigned char* pool = nullptr;
    cudaGetSymbolAddress((void**)&pool, g_pool);

    __half*  q_bf    = (__half*)(pool + OFF_Q_BF);
    __half*  kv_bf   = (__half*)(pool + OFF_KV_BF);
    __half*  qin_bf  = (__half*)(pool + OFF_QIN_BF);
    __half*  kvin_bf = (__half*)(pool + OFF_KVIN_BF);
    __half*  att_bf  = (__half*)(pool + OFF_ATT_BF);
    __half*  x1h     = (__half*)(pool + OFF_X1_H);
    __half*  wq_bf   = (__half*)(pool + OFF_WQ_BF);
    __half*  wkv_bf  = (__half*)(pool + OFF_WKV_BF);
    __half*  wp_bf   = (__half*)(pool + OFF_W_P_BF);
    __half*  w1_bf   = (__half*)(pool + OFF_W1_BF);
    __half*  w2_bf   = (__half*)(pool + OFF_W2_BF);
    float*   biasf   = (float*)(pool + OFF_BIASF);
    __half*  hid_bf  = (__half*)(pool + OFF_HID_BF);
    __half*  yn_bf   = (__half*)(pool + OFF_YN_BF);

    cudaFuncSetAttribute(gemm_mma<2>, cudaFuncAttributeMaxDynamicSharedMemorySize, GEMM_SMEM);
    cudaFuncSetAttribute(gemm_mma<3>, cudaFuncAttributeMaxDynamicSharedMemorySize, GEMM_SMEM);
    cudaFuncSetAttribute(gemm_mma<4>, cudaFuncAttributeMaxDynamicSharedMemorySize, GEMM_SMEM);
    cudaFuncSetAttribute(gemm_mma<5>, cudaFuncAttributeMaxDynamicSharedMemorySize, GEMM_SMEM);
    cudaFuncSetAttribute(attn_mma_kernel, cudaFuncAttributeMaxDynamicSharedMemorySize, ATT_SMEM);

    // 0. weights + bias expansion (one launch, 400 blocks)
    convall_kernel<<<400, 256>>>(qw, kvw, pw, w1, w2, bias_table,
                                 wq_bf, wkv_bf, wp_bf, w1_bf, w2_bf, biasf);

    // 1. LN1 + shift + window partition (fp16 tiles only)
    ln1_win_kernel<<<(2 * 2 * 256 * 256) / 8, 256>>>(x, g1, b1, qin_bf, kvin_bf);

    // 2. Fused Q + KV GEMM
    gemm_mma<5><<<dim3(6, 1024), 128, GEMM_SMEM>>>(qin_bf, wq_bf, qb, q_bf, 256,
                                                   nullptr, nullptr,
                                                   kvin_bf, wkv_bf, kvb, kv_bf);

    // 3. tensor-core attention -> att fp16 tiles
    attn_mma_kernel<<<2048, 256, ATT_SMEM>>>(q_bf, kv_bf, att_bf, mask, biasf);

    // 4. proj + residual(qin tiles) + shortcut(x) + inverse-roll scatter -> x1 fp16
    gemm_mma<2><<<dim3(2, 1024), 128, GEMM_SMEM>>>(att_bf, wp_bf, pb, x1h, 256,
                                                   qin_bf, x, nullptr, nullptr, nullptr, nullptr);

    // 5. LN2 (fp16 in) -> yn fp16 tiles
    ln2_kernel<<<ROWS / 8, 256>>>(x1h, g2, b2, yn_bf);

    // 6. MLP1 + gelu -> hid fp16 tiles
    gemm_mma<3><<<dim3(8, 1024), 128, GEMM_SMEM>>>(yn_bf, w1_bf, bi1, hid_bf, 256,
                                                   nullptr, nullptr, nullptr, nullptr, nullptr, nullptr);

    // 7. MLP2 + residual(x1 fp16) -> out fp32
    gemm_mma<4><<<dim3(2, 1024), 128, GEMM_SMEM>>>(hid_bf, w2_bf, bi2, out, 1024,
                                                   x1h, nullptr, nullptr, nullptr, nullptr, nullptr);
}